// round 8
// baseline (speedup 1.0000x reference)
#include <cuda_runtime.h>
#include <cuda_bf16.h>
#include <cuda_pipeline.h>
#include <mma.h>
#include <math.h>

#define LL 64
#define NB 8
#define HD 512
#define NV 8192
#define NP 2016                       // L*(L-1)/2 pairs
#define NROW ((NP + 1) * NB)          // 16136 rows (pairs + the (0,0) cell)
#define NROW_PAD (127 * 128)          // 16256, padded to GEMM row tiles
#define NEGV (-1e9f)
#define EPSV 4.5399929762484854e-05f  // exp(-10)

using namespace nvcuda;

// ------------------------- device scratch -------------------------
__device__ float g_At[LL * NB * HD];      // enc @ W1t[:H]
__device__ float g_Bt[LL * NB * HD];      // enc @ W1t[H:]
__device__ float g_Aw[LL * NB * HD];      // enc @ W1w[:H]
__device__ float g_Bw[LL * NB * HD];      // enc @ W1w[H:]
__device__ __nv_bfloat16 g_hwb[NROW_PAD * HD];   // relu hidden (bf16) for word head
__device__ __nv_bfloat16 g_W2wb[HD * NV];        // W2w in bf16
__device__ float g_shlog[NP * NB];        // log1p(-p + EPS)
__device__ float g_relog[NP * NB];        // log(p + EPS)
__device__ float g_sum[NROW_PAD];         // sum of exp(logit) per row
__device__ float g_gw[NROW];              // gathered word logit per row
__device__ float g_table[LL * LL * LL * NB];
__device__ int g_bar[LL];                 // per-gap arrival counters (zeroed each call)

__device__ __forceinline__ int pidx(int i, int j) {
    return i * (2 * LL - 1 - i) / 2 + (j - i - 1);
}

__device__ __forceinline__ int inv_pair(int p, int& j) {
    int i = 0;
    while (p >= (LL - 1 - i)) { p -= (LL - 1 - i); i++; }
    j = i + 1 + p;
    return i;
}

// ------------------------- init + W2w->bf16 (merged, one launch) ---------------
__global__ void init_all(const float* __restrict__ W) {
    int idx = blockIdx.x * 256 + threadIdx.x;
    if (idx < LL * LL * LL * NB) g_table[idx] = NEGV;
    if (idx < NROW_PAD) g_sum[idx] = 0.f;
    if (idx < (NROW_PAD - NROW) * HD) g_hwb[NROW * HD + idx] = __float2bfloat16(0.f);
    if (idx < LL) g_bar[idx] = 0;
    if (idx < (HD * NV) / 4) {
        int i = idx * 4;
        float4 v = *(const float4*)(W + i);
        __nv_bfloat16 o[4];
        o[0] = __float2bfloat16(v.x);
        o[1] = __float2bfloat16(v.y);
        o[2] = __float2bfloat16(v.z);
        o[3] = __float2bfloat16(v.w);
        *(unsigned long long*)(&g_W2wb[i]) = *(unsigned long long*)o;
    }
}

// ------------------------- enc projections (all 4 in one launch) -------------------------
__global__ void proj_gemm(const float* __restrict__ A, const float* __restrict__ W1t,
                          const float* __restrict__ W1w) {
    int which = blockIdx.z;
    const float* W = (which < 2) ? W1t : W1w;
    int koff = (which & 1) * HD;
    float* C = (which == 0) ? g_At : (which == 1) ? g_Bt : (which == 2) ? g_Aw : g_Bw;
    __shared__ float As[16][64];
    __shared__ float Bs[16][64];
    int tid = threadIdx.x;
    int tc = tid & 15, tr = tid >> 4;
    int rb = blockIdx.y * 64, cb = blockIdx.x * 64;
    float acc[4][4];
    for (int i = 0; i < 4; i++)
        for (int q = 0; q < 4; q++) acc[i][q] = 0.f;

    for (int k0 = 0; k0 < HD; k0 += 16) {
        for (int l = tid; l < 1024; l += 256) {
            int r = l >> 4, c = l & 15;
            As[c][r] = A[(rb + r) * HD + k0 + c];
        }
        for (int l = tid; l < 1024; l += 256) {
            int r = l >> 6, c = l & 63;
            Bs[r][c] = W[(koff + k0 + r) * HD + cb + c];
        }
        __syncthreads();
        for (int kk = 0; kk < 16; kk++) {
            float av[4], bv[4];
            for (int i = 0; i < 4; i++) av[i] = As[kk][tr * 4 + i];
            for (int q = 0; q < 4; q++) bv[q] = Bs[kk][tc * 4 + q];
            for (int i = 0; i < 4; i++)
                for (int q = 0; q < 4; q++) acc[i][q] = fmaf(av[i], bv[q], acc[i][q]);
        }
        __syncthreads();
    }
    for (int i = 0; i < 4; i++)
        for (int q = 0; q < 4; q++)
            C[(rb + tr * 4 + i) * HD + cb + tc * 4 + q] = acc[i][q];
}

// ------------------------- per-pair MLP heads -------------------------
__global__ void pair_kernel(const float* __restrict__ b1t, const float* __restrict__ W2t,
                            const float* __restrict__ b2t, const float* __restrict__ b1w) {
    int p = blockIdx.x;
    int i = 0, j = 0;
    if (p < NP) i = inv_pair(p, j);
    int w = threadIdx.x >> 5;
    int lane = threadIdx.x & 31;
    const float* Ar = &g_Aw[(i * NB + w) * HD];
    const float* Br = &g_Bw[(j * NB + w) * HD];
    const float* At = &g_At[(i * NB + w) * HD];
    const float* Bt = &g_Bt[(j * NB + w) * HD];
    __nv_bfloat16* hwrow = &g_hwb[(p * NB + w) * HD];
    float part = 0.f;
    for (int t = 0; t < 16; t++) {
        int h = lane + t * 32;
        float hw = fmaxf(Ar[h] + Br[h] + b1w[h], 0.f);
        hwrow[h] = __float2bfloat16(hw);
        if (p < NP) {
            float ht = fmaxf(At[h] + Bt[h] + b1t[h], 0.f);
            part = fmaf(ht, W2t[h], part);
        }
    }
    if (p < NP) {
        for (int o = 16; o; o >>= 1) part += __shfl_xor_sync(0xffffffffu, part, o);
        if (lane == 0) {
            float z = part + b2t[0];
            float s = 1.f / (1.f + expf(-z));
            g_shlog[p * NB + w] = log1pf(-s + EPSV);
            g_relog[p * NB + w] = logf(s + EPSV);
        }
    }
}

// ------------------------- wmma GEMM + sum(exp), cp.async double buffer --------
// C = hwb[16256,512] @ W2wb[512,8192] (bf16 -> f32); per row accumulate
// sum_v exp(c + b2w[v]) into g_sum via atomicAdd (32 column blocks).
// Tiles: BM=128, BN=256, BK=32. 8 warps as 2 (m) x 4 (n); warp tile 64x64.
// Global->smem tiles move via cp.async (no LDG/STS register round trip).
#define AS_LD 40
#define BS_LD 264
__global__ void __launch_bounds__(256) gemm_lse_wmma(const float* __restrict__ b2w) {
    __shared__ __align__(128) __nv_bfloat16 As[2][128 * AS_LD];
    __shared__ __align__(128) __nv_bfloat16 Bs[2][32 * BS_LD];
    __shared__ __align__(128) float stage[8 * 256];   // 1KB per warp
    int tid = threadIdx.x;
    int wid = tid >> 5, lane = tid & 31;
    int wm = wid >> 2, wn = wid & 3;
    int rowBase = blockIdx.x * 128;
    int v0 = blockIdx.y * 256;

    // per-thread copy coordinates
    int ar0 = tid >> 2, ac0 = (tid & 3) * 8;              // A: 512 uint4, 2/thread
    int ar1 = (tid + 256) >> 2, ac1 = ((tid + 256) & 3) * 8;
    int bk[4], bn[4];                                     // B: 1024 uint4, 4/thread
    for (int l = 0; l < 4; l++) {
        int idx = tid + l * 256;
        bk[l] = idx >> 5;
        bn[l] = (idx & 31) * 8;
    }

    wmma::fragment<wmma::accumulator, 16, 16, 16, float> acc[4][4];
    for (int mt = 0; mt < 4; mt++)
        for (int nt = 0; nt < 4; nt++) wmma::fill_fragment(acc[mt][nt], 0.f);

    // prologue: async-copy k-tile 0 into buffer 0
    __pipeline_memcpy_async(&As[0][ar0 * AS_LD + ac0], &g_hwb[(rowBase + ar0) * HD + ac0], 16);
    __pipeline_memcpy_async(&As[0][ar1 * AS_LD + ac1], &g_hwb[(rowBase + ar1) * HD + ac1], 16);
    for (int l = 0; l < 4; l++)
        __pipeline_memcpy_async(&Bs[0][bk[l] * BS_LD + bn[l]], &g_W2wb[bk[l] * NV + v0 + bn[l]], 16);
    __pipeline_commit();

    int buf = 0;
    for (int kt = 0; kt < 16; kt++) {
        __syncthreads();   // all reads of buf^1 (previous compute) complete
        if (kt + 1 < 16) {
            int k0 = (kt + 1) * 32;
            int nb = buf ^ 1;
            __pipeline_memcpy_async(&As[nb][ar0 * AS_LD + ac0],
                                    &g_hwb[(rowBase + ar0) * HD + k0 + ac0], 16);
            __pipeline_memcpy_async(&As[nb][ar1 * AS_LD + ac1],
                                    &g_hwb[(rowBase + ar1) * HD + k0 + ac1], 16);
            for (int l = 0; l < 4; l++)
                __pipeline_memcpy_async(&Bs[nb][bk[l] * BS_LD + bn[l]],
                                        &g_W2wb[(k0 + bk[l]) * NV + v0 + bn[l]], 16);
            __pipeline_commit();
            __pipeline_wait_prior(1);   // tile kt landed; kt+1 still in flight
        } else {
            __pipeline_wait_prior(0);
        }
        __syncthreads();   // tile kt visible to all threads

        for (int kk = 0; kk < 32; kk += 16) {
            wmma::fragment<wmma::matrix_a, 16, 16, 16, __nv_bfloat16, wmma::row_major> af[4];
            wmma::fragment<wmma::matrix_b, 16, 16, 16, __nv_bfloat16, wmma::row_major> bf[4];
            for (int mt = 0; mt < 4; mt++)
                wmma::load_matrix_sync(af[mt], &As[buf][(wm * 64 + mt * 16) * AS_LD + kk], AS_LD);
            for (int nt = 0; nt < 4; nt++)
                wmma::load_matrix_sync(bf[nt], &Bs[buf][kk * BS_LD + wn * 64 + nt * 16], BS_LD);
            for (int mt = 0; mt < 4; mt++)
                for (int nt = 0; nt < 4; nt++)
                    wmma::mma_sync(acc[mt][nt], af[mt], bf[nt], acc[mt][nt]);
        }
        buf ^= 1;
    }

    // epilogue: stage each 16x16 tile, exp + row-reduce, atomicAdd per row
    float* st = &stage[wid * 256];
    int r = lane & 15, half = lane >> 4;
    float rs[4];
    for (int mt = 0; mt < 4; mt++) rs[mt] = 0.f;
    for (int mt = 0; mt < 4; mt++) {
        for (int nt = 0; nt < 4; nt++) {
            wmma::store_matrix_sync(st, acc[mt][nt], 16, wmma::mem_row_major);
            __syncwarp();
            int cb = v0 + wn * 64 + nt * 16 + half * 8;
            float s = 0.f;
            for (int c = 0; c < 8; c++)
                s += __expf(st[r * 16 + half * 8 + c] + b2w[cb + c]);
            s += __shfl_xor_sync(0xffffffffu, s, 16);
            rs[mt] += s;
            __syncwarp();
        }
    }
    if (lane < 16) {
        for (int mt = 0; mt < 4; mt++)
            atomicAdd(&g_sum[rowBase + wm * 64 + mt * 16 + lane], rs[mt]);
    }
}

// ------------------------- gathered word logit -------------------------
__global__ void gather_kernel(const int* __restrict__ sentence,
                              const float* __restrict__ b2w) {
    int row = blockIdx.x * 8 + (threadIdx.x >> 5);
    int lane = threadIdx.x & 31;
    if (row >= NROW) return;
    int p = row >> 3, b = row & 7;
    int jw;
    if (p < NP) { int j; inv_pair(p, j); jw = (j + 1 < LL) ? j + 1 : 0; }
    else jw = 1;  // (0,0) cell uses sentence[1]
    int word = sentence[jw * NB + b];
    const __nv_bfloat16* hwrow = &g_hwb[row * HD];
    float part = 0.f;
    for (int tt = 0; tt < 16; tt++) {
        int h = lane + tt * 32;
        part = fmaf(__bfloat162float(hwrow[h]),
                    __bfloat162float(g_W2wb[h * NV + word]), part);
    }
    for (int o = 16; o; o >>= 1) part += __shfl_xor_sync(0xffffffffu, part, o);
    if (lane == 0) g_gw[row] = part + b2w[word];
}

// ------------------------- DP base cells -------------------------
__global__ void base_kernel() {
    int idx = blockIdx.x * 256 + threadIdx.x;
    if (idx < NP * NB) {
        int p = idx >> 3, b = idx & 7;
        int j;
        int i = inv_pair(p, j);
        if (j <= LL - 2) {
            float lse = logf(g_sum[idx]);
            g_table[((i * LL + j) * LL + (j + 1)) * NB + b] =
                g_shlog[idx] + g_gw[idx] - lse;
        }
    } else if (idx < NP * NB + NB) {
        int b = idx - NP * NB;
        int rr = NP * NB + b;
        g_table[(0 * LL + 1) * NB + b] = g_gw[rr] - logf(g_sum[rr]);
    }
}

// ------------------------- full inside recursion, one persistent launch --------
// 62 blocks (all co-resident: 62 < 148 SMs), global spin barrier per gap.
__global__ void dp_all(float* __restrict__ out) {
    int blk = blockIdx.x;
    int tid = threadIdx.x;
    __shared__ float right[62 * 8];
    for (int gap = 2; gap <= LL - 1; gap++) {
        int nblk = LL - gap;
        if (blk < nblk) {
            int iv = blk;
            int jv = iv + gap;
            int nk = gap - 1;
            for (int m = tid; m < nk * 8; m += 512) {
                int d = m >> 3, b = m & 7;
                int k = iv + 1 + d;
                right[m] = g_table[((iv * LL + k) * LL + jv) * NB + b] +
                           g_relog[pidx(k, jv) * NB + b];
            }
            __syncthreads();
            int b = tid & 7, l = tid >> 3;
            const float* base = &g_table[(l * LL + iv) * LL * NB + b];
            float mx = -3.0e38f, s = 0.f;
            for (int d = 0; d < nk; d++) {
                int k = iv + 1 + d;
                float x = base[k * NB] + right[d * 8 + b];
                if (x > mx) { s = s * __expf(mx - x) + 1.f; mx = x; }
                else s += __expf(x - mx);
            }
            g_table[((l * LL + iv) * LL + jv) * NB + b] = mx + logf(s);
            __syncthreads();   // 'right' reused next gap
        }
        // grid-wide barrier for this gap
        if (tid == 0) {
            __threadfence();
            atomicAdd(&g_bar[gap], 1);
            while (*((volatile int*)&g_bar[gap]) < (int)gridDim.x) {}
            __threadfence();
        }
        __syncthreads();
    }
    if (blk == 0 && tid < NB)
        out[tid] = g_table[(0 * LL + (LL - 1)) * NB + tid];
}

// ------------------------- launch -------------------------
extern "C" void kernel_launch(void* const* d_in, const int* in_sizes, int n_in,
                              void* d_out, int out_size) {
    const float* enc = (const float*)d_in[0];
    const int* sentence = (const int*)d_in[1];
    const float* W1t = (const float*)d_in[2];
    const float* b1t = (const float*)d_in[3];
    const float* W2t = (const float*)d_in[4];
    const float* b2t = (const float*)d_in[5];
    const float* W1w = (const float*)d_in[6];
    const float* b1w = (const float*)d_in[7];
    const float* W2w = (const float*)d_in[8];
    const float* b2w = (const float*)d_in[9];
    float* out = (float*)d_out;

    init_all<<<8192, 256>>>(W2w);                       // launch 1
    proj_gemm<<<dim3(8, 8, 4), 256>>>(enc, W1t, W1w);   // launch 2
    pair_kernel<<<NP + 1, 256>>>(b1t, W2t, b2t, b1w);   // launch 3
    gemm_lse_wmma<<<dim3(127, 32), 256>>>(b2w);         // launch 4  (ncu target)
    gather_kernel<<<(NROW + 7) / 8, 256>>>(sentence, b2w);
    base_kernel<<<64, 256>>>();
    dp_all<<<62, 512>>>(out);
}

// round 9
// speedup vs baseline: 1.0489x; 1.0489x over previous
#include <cuda_runtime.h>
#include <cuda_bf16.h>
#include <cuda_pipeline.h>
#include <mma.h>
#include <math.h>

#define LL 64
#define NB 8
#define HD 512
#define NV 8192
#define NP 2016                       // L*(L-1)/2 pairs
#define NROW ((NP + 1) * NB)          // 16136 rows (pairs + the (0,0) cell)
#define NROW_PAD (127 * 128)          // 16256, padded to GEMM row tiles
#define NEGV (-1e9f)
#define EPSV 4.5399929762484854e-05f  // exp(-10)

using namespace nvcuda;

// ------------------------- device scratch -------------------------
__device__ float g_At[LL * NB * HD];      // enc @ W1t[:H]
__device__ float g_Bt[LL * NB * HD];      // enc @ W1t[H:]
__device__ float g_Aw[LL * NB * HD];      // enc @ W1w[:H]
__device__ float g_Bw[LL * NB * HD];      // enc @ W1w[H:]
__device__ __nv_bfloat16 g_hwb[NROW_PAD * HD];   // relu hidden (bf16) for word head
__device__ __nv_bfloat16 g_W2wb[HD * NV];        // W2w in bf16
__device__ float g_shlog[NP * NB];        // log1p(-p + EPS)
__device__ float g_relog[NP * NB];        // log(p + EPS)
__device__ float g_sum[NROW_PAD];         // sum of exp(logit) per row
__device__ float g_table[LL * LL * LL * NB];
__device__ int g_bar[LL];                 // per-gap arrival counters (zeroed each call)

__device__ __forceinline__ int pidx(int i, int j) {
    return i * (2 * LL - 1 - i) / 2 + (j - i - 1);
}

__device__ __forceinline__ int inv_pair(int p, int& j) {
    int i = 0;
    while (p >= (LL - 1 - i)) { p -= (LL - 1 - i); i++; }
    j = i + 1 + p;
    return i;
}

// ------------------------- init + W2w->bf16 (merged, one launch) ---------------
__global__ void init_all(const float* __restrict__ W) {
    int idx = blockIdx.x * 256 + threadIdx.x;
    if (idx < LL * LL * LL * NB) g_table[idx] = NEGV;
    if (idx < NROW_PAD) g_sum[idx] = 0.f;
    if (idx < (NROW_PAD - NROW) * HD) g_hwb[NROW * HD + idx] = __float2bfloat16(0.f);
    if (idx < LL) g_bar[idx] = 0;
    if (idx < (HD * NV) / 4) {
        int i = idx * 4;
        float4 v = *(const float4*)(W + i);
        __nv_bfloat16 o[4];
        o[0] = __float2bfloat16(v.x);
        o[1] = __float2bfloat16(v.y);
        o[2] = __float2bfloat16(v.z);
        o[3] = __float2bfloat16(v.w);
        *(unsigned long long*)(&g_W2wb[i]) = *(unsigned long long*)o;
    }
}

// ------------------------- enc projections (all 4 in one launch) -------------------------
__global__ void proj_gemm(const float* __restrict__ A, const float* __restrict__ W1t,
                          const float* __restrict__ W1w) {
    int which = blockIdx.z;
    const float* W = (which < 2) ? W1t : W1w;
    int koff = (which & 1) * HD;
    float* C = (which == 0) ? g_At : (which == 1) ? g_Bt : (which == 2) ? g_Aw : g_Bw;
    __shared__ float As[16][64];
    __shared__ float Bs[16][64];
    int tid = threadIdx.x;
    int tc = tid & 15, tr = tid >> 4;
    int rb = blockIdx.y * 64, cb = blockIdx.x * 64;
    float acc[4][4];
    for (int i = 0; i < 4; i++)
        for (int q = 0; q < 4; q++) acc[i][q] = 0.f;

    for (int k0 = 0; k0 < HD; k0 += 16) {
        for (int l = tid; l < 1024; l += 256) {
            int r = l >> 4, c = l & 15;
            As[c][r] = A[(rb + r) * HD + k0 + c];
        }
        for (int l = tid; l < 1024; l += 256) {
            int r = l >> 6, c = l & 63;
            Bs[r][c] = W[(koff + k0 + r) * HD + cb + c];
        }
        __syncthreads();
        for (int kk = 0; kk < 16; kk++) {
            float av[4], bv[4];
            for (int i = 0; i < 4; i++) av[i] = As[kk][tr * 4 + i];
            for (int q = 0; q < 4; q++) bv[q] = Bs[kk][tc * 4 + q];
            for (int i = 0; i < 4; i++)
                for (int q = 0; q < 4; q++) acc[i][q] = fmaf(av[i], bv[q], acc[i][q]);
        }
        __syncthreads();
    }
    for (int i = 0; i < 4; i++)
        for (int q = 0; q < 4; q++)
            C[(rb + tr * 4 + i) * HD + cb + tc * 4 + q] = acc[i][q];
}

// ------------------------- per-pair MLP heads -------------------------
__global__ void pair_kernel(const float* __restrict__ b1t, const float* __restrict__ W2t,
                            const float* __restrict__ b2t, const float* __restrict__ b1w) {
    int p = blockIdx.x;
    int i = 0, j = 0;
    if (p < NP) i = inv_pair(p, j);
    int w = threadIdx.x >> 5;
    int lane = threadIdx.x & 31;
    const float* Ar = &g_Aw[(i * NB + w) * HD];
    const float* Br = &g_Bw[(j * NB + w) * HD];
    const float* At = &g_At[(i * NB + w) * HD];
    const float* Bt = &g_Bt[(j * NB + w) * HD];
    __nv_bfloat16* hwrow = &g_hwb[(p * NB + w) * HD];
    float part = 0.f;
    for (int t = 0; t < 16; t++) {
        int h = lane + t * 32;
        float hw = fmaxf(Ar[h] + Br[h] + b1w[h], 0.f);
        hwrow[h] = __float2bfloat16(hw);
        if (p < NP) {
            float ht = fmaxf(At[h] + Bt[h] + b1t[h], 0.f);
            part = fmaf(ht, W2t[h], part);
        }
    }
    if (p < NP) {
        for (int o = 16; o; o >>= 1) part += __shfl_xor_sync(0xffffffffu, part, o);
        if (lane == 0) {
            float z = part + b2t[0];
            float s = 1.f / (1.f + expf(-z));
            g_shlog[p * NB + w] = log1pf(-s + EPSV);
            g_relog[p * NB + w] = logf(s + EPSV);
        }
    }
}

// ------------------------- wmma GEMM + sum(exp), cp.async, occupancy 2 ---------
// C = hwb[16256,512] @ W2wb[512,8192] (bf16 -> f32); per row accumulate
// sum_v exp(c + b2w[v]) into g_sum via atomicAdd (64 column blocks).
// Tiles: BM=128, BN=128, BK=32. 8 warps as 2 (m) x 4 (n); warp tile 64x32
// (acc[4][2]) -> ~108 regs, forced <=128 so TWO blocks co-reside per SM
// (4 warps per SMSP hides ldmatrix/sync latency; tensor pipe was 33% busy
//  at 2 warps/SMSP).
#define AS_LD 40
#define BS_LD 136
__global__ void __launch_bounds__(256, 2) gemm_lse_wmma(const float* __restrict__ b2w) {
    __shared__ __align__(128) __nv_bfloat16 As[2][128 * AS_LD];
    __shared__ __align__(128) __nv_bfloat16 Bs[2][32 * BS_LD];
    __shared__ __align__(128) float stage[8 * 256];   // 1KB per warp
    int tid = threadIdx.x;
    int wid = tid >> 5, lane = tid & 31;
    int wm = wid >> 2, wn = wid & 3;
    int rowBase = blockIdx.x * 128;
    int v0 = blockIdx.y * 128;

    // per-thread copy coordinates (A: 512 uint4, B: 512 uint4 -> 2 each/thread)
    int ar0 = tid >> 2, ac0 = (tid & 3) * 8;
    int ar1 = (tid + 256) >> 2, ac1 = ((tid + 256) & 3) * 8;
    int bk0 = tid >> 4, bn0 = (tid & 15) * 8;
    int bk1 = (tid + 256) >> 4, bn1 = ((tid + 256) & 15) * 8;

    wmma::fragment<wmma::accumulator, 16, 16, 16, float> acc[4][2];
    for (int mt = 0; mt < 4; mt++)
        for (int nt = 0; nt < 2; nt++) wmma::fill_fragment(acc[mt][nt], 0.f);

    // prologue: async-copy k-tile 0 into buffer 0
    __pipeline_memcpy_async(&As[0][ar0 * AS_LD + ac0], &g_hwb[(rowBase + ar0) * HD + ac0], 16);
    __pipeline_memcpy_async(&As[0][ar1 * AS_LD + ac1], &g_hwb[(rowBase + ar1) * HD + ac1], 16);
    __pipeline_memcpy_async(&Bs[0][bk0 * BS_LD + bn0], &g_W2wb[bk0 * NV + v0 + bn0], 16);
    __pipeline_memcpy_async(&Bs[0][bk1 * BS_LD + bn1], &g_W2wb[bk1 * NV + v0 + bn1], 16);
    __pipeline_commit();

    int buf = 0;
    for (int kt = 0; kt < 16; kt++) {
        __syncthreads();   // all reads of buf^1 (previous compute) complete
        if (kt + 1 < 16) {
            int k0 = (kt + 1) * 32;
            int nb = buf ^ 1;
            __pipeline_memcpy_async(&As[nb][ar0 * AS_LD + ac0],
                                    &g_hwb[(rowBase + ar0) * HD + k0 + ac0], 16);
            __pipeline_memcpy_async(&As[nb][ar1 * AS_LD + ac1],
                                    &g_hwb[(rowBase + ar1) * HD + k0 + ac1], 16);
            __pipeline_memcpy_async(&Bs[nb][bk0 * BS_LD + bn0],
                                    &g_W2wb[(k0 + bk0) * NV + v0 + bn0], 16);
            __pipeline_memcpy_async(&Bs[nb][bk1 * BS_LD + bn1],
                                    &g_W2wb[(k0 + bk1) * NV + v0 + bn1], 16);
            __pipeline_commit();
            __pipeline_wait_prior(1);   // tile kt landed; kt+1 still in flight
        } else {
            __pipeline_wait_prior(0);
        }
        __syncthreads();   // tile kt visible to all threads

        for (int kk = 0; kk < 32; kk += 16) {
            wmma::fragment<wmma::matrix_a, 16, 16, 16, __nv_bfloat16, wmma::row_major> af[4];
            wmma::fragment<wmma::matrix_b, 16, 16, 16, __nv_bfloat16, wmma::row_major> bf[2];
            for (int mt = 0; mt < 4; mt++)
                wmma::load_matrix_sync(af[mt], &As[buf][(wm * 64 + mt * 16) * AS_LD + kk], AS_LD);
            for (int nt = 0; nt < 2; nt++)
                wmma::load_matrix_sync(bf[nt], &Bs[buf][kk * BS_LD + wn * 32 + nt * 16], BS_LD);
            for (int mt = 0; mt < 4; mt++)
                for (int nt = 0; nt < 2; nt++)
                    wmma::mma_sync(acc[mt][nt], af[mt], bf[nt], acc[mt][nt]);
        }
        buf ^= 1;
    }

    // epilogue: stage each 16x16 tile, exp + row-reduce, atomicAdd per row
    float* st = &stage[wid * 256];
    int r = lane & 15, half = lane >> 4;
    float rs[4];
    for (int mt = 0; mt < 4; mt++) rs[mt] = 0.f;
    for (int mt = 0; mt < 4; mt++) {
        for (int nt = 0; nt < 2; nt++) {
            wmma::store_matrix_sync(st, acc[mt][nt], 16, wmma::mem_row_major);
            __syncwarp();
            int cb = v0 + wn * 32 + nt * 16 + half * 8;
            float s = 0.f;
            for (int c = 0; c < 8; c++)
                s += __expf(st[r * 16 + half * 8 + c] + b2w[cb + c]);
            s += __shfl_xor_sync(0xffffffffu, s, 16);
            rs[mt] += s;
            __syncwarp();
        }
    }
    if (lane < 16) {
        for (int mt = 0; mt < 4; mt++)
            atomicAdd(&g_sum[rowBase + wm * 64 + mt * 16 + lane], rs[mt]);
    }
}

// ------------------------- gathered word logit + DP base cells (fused) ---------
__global__ void gather_base(const int* __restrict__ sentence,
                            const float* __restrict__ b2w) {
    int row = blockIdx.x * 8 + (threadIdx.x >> 5);
    int lane = threadIdx.x & 31;
    if (row >= NROW) return;
    int p = row >> 3, b = row & 7;
    int jw, i = 0, j = 0;
    if (p < NP) { i = inv_pair(p, j); jw = (j + 1 < LL) ? j + 1 : 0; }
    else jw = 1;  // (0,0) cell uses sentence[1]
    int word = sentence[jw * NB + b];
    const __nv_bfloat16* hwrow = &g_hwb[row * HD];
    float part = 0.f;
    for (int tt = 0; tt < 16; tt++) {
        int h = lane + tt * 32;
        part = fmaf(__bfloat162float(hwrow[h]),
                    __bfloat162float(g_W2wb[h * NV + word]), part);
    }
    for (int o = 16; o; o >>= 1) part += __shfl_xor_sync(0xffffffffu, part, o);
    if (lane == 0) {
        float gw = part + b2w[word];
        float lse = logf(g_sum[row]);
        if (p < NP) {
            if (j <= LL - 2)
                g_table[((i * LL + j) * LL + (j + 1)) * NB + b] =
                    g_shlog[row] + gw - lse;
        } else {
            g_table[(0 * LL + 1) * NB + b] = gw - lse;   // table[0,0,1]
        }
    }
}

// ------------------------- full inside recursion, one persistent launch --------
// 62 blocks (all co-resident: 62 < 148 SMs), global spin barrier per gap.
__global__ void dp_all(float* __restrict__ out) {
    int blk = blockIdx.x;
    int tid = threadIdx.x;
    __shared__ float right[62 * 8];
    for (int gap = 2; gap <= LL - 1; gap++) {
        int nblk = LL - gap;
        if (blk < nblk) {
            int iv = blk;
            int jv = iv + gap;
            int nk = gap - 1;
            for (int m = tid; m < nk * 8; m += 512) {
                int d = m >> 3, b = m & 7;
                int k = iv + 1 + d;
                right[m] = g_table[((iv * LL + k) * LL + jv) * NB + b] +
                           g_relog[pidx(k, jv) * NB + b];
            }
            __syncthreads();
            int b = tid & 7, l = tid >> 3;
            const float* base = &g_table[(l * LL + iv) * LL * NB + b];
            float mx = -3.0e38f, s = 0.f;
            for (int d = 0; d < nk; d++) {
                int k = iv + 1 + d;
                float x = base[k * NB] + right[d * 8 + b];
                if (x > mx) { s = s * __expf(mx - x) + 1.f; mx = x; }
                else s += __expf(x - mx);
            }
            g_table[((l * LL + iv) * LL + jv) * NB + b] = mx + logf(s);
            __syncthreads();   // 'right' reused next gap
        }
        // grid-wide barrier for this gap
        if (tid == 0) {
            __threadfence();
            atomicAdd(&g_bar[gap], 1);
            while (*((volatile int*)&g_bar[gap]) < (int)gridDim.x) {}
            __threadfence();
        }
        __syncthreads();
    }
    if (blk == 0 && tid < NB)
        out[tid] = g_table[(0 * LL + (LL - 1)) * NB + tid];
}

// ------------------------- launch -------------------------
extern "C" void kernel_launch(void* const* d_in, const int* in_sizes, int n_in,
                              void* d_out, int out_size) {
    const float* enc = (const float*)d_in[0];
    const int* sentence = (const int*)d_in[1];
    const float* W1t = (const float*)d_in[2];
    const float* b1t = (const float*)d_in[3];
    const float* W2t = (const float*)d_in[4];
    const float* b2t = (const float*)d_in[5];
    const float* W1w = (const float*)d_in[6];
    const float* b1w = (const float*)d_in[7];
    const float* W2w = (const float*)d_in[8];
    const float* b2w = (const float*)d_in[9];
    float* out = (float*)d_out;

    init_all<<<8192, 256>>>(W2w);                       // launch 1
    proj_gemm<<<dim3(8, 8, 4), 256>>>(enc, W1t, W1w);   // launch 2
    pair_kernel<<<NP + 1, 256>>>(b1t, W2t, b2t, b1w);   // launch 3
    gemm_lse_wmma<<<dim3(127, 64), 256>>>(b2w);         // launch 4  (ncu target)
    gather_base<<<(NROW + 7) / 8, 256>>>(sentence, b2w);
    dp_all<<<62, 512>>>(out);
}

// round 11
// speedup vs baseline: 1.3942x; 1.3292x over previous
#include <cuda_runtime.h>
#include <cuda_bf16.h>
#include <cuda_pipeline.h>
#include <math.h>

#define LL 64
#define NB 8
#define HD 512
#define NV 8192
#define NP 2016                       // L*(L-1)/2 pairs
#define NROW ((NP + 1) * NB)          // 16136 rows (pairs + the (0,0) cell)
#define NROW_PAD (127 * 128)          // 16256, padded to GEMM row tiles
#define NEGV (-1e9f)
#define EPSV 4.5399929762484854e-05f  // exp(-10)

// ------------------------- device scratch -------------------------
__device__ float g_At[LL * NB * HD];
__device__ float g_Bt[LL * NB * HD];
__device__ float g_Aw[LL * NB * HD];
__device__ float g_Bw[LL * NB * HD];
__device__ __nv_bfloat16 g_hwb[NROW_PAD * HD];   // relu hidden (bf16)
__device__ __nv_bfloat16 g_W2wb[HD * NV];        // W2w in bf16, k-major [k][v]
__device__ float g_shlog[NP * NB];
__device__ float g_relog[NP * NB];
__device__ float g_sum[NROW_PAD];
__device__ float g_table[LL * LL * LL * NB];
__device__ int g_bar[LL];

__device__ __forceinline__ int pidx(int i, int j) {
    return i * (2 * LL - 1 - i) / 2 + (j - i - 1);
}

__device__ __forceinline__ int inv_pair(int p, int& j) {
    int i = 0;
    while (p >= (LL - 1 - i)) { p -= (LL - 1 - i); i++; }
    j = i + 1 + p;
    return i;
}

// ------------------------- sanitized PTX helpers (no Jinja-active tokens) ------
__device__ __forceinline__ unsigned int smem_u32(const void* p) {
    unsigned int a;
    asm("{ .reg .u64 t; cvta.to.shared.u64 t, %1; cvt.u32.u64 %0, t; }"
        : "=r"(a) : "l"(p));
    return a;
}

__device__ __forceinline__ void ldsm_x4(unsigned int& r0, unsigned int& r1,
                                        unsigned int& r2, unsigned int& r3,
                                        unsigned int addr) {
    asm volatile(
        "ldmatrix.sync.aligned.m8n8.x4.shared.b16 { %0, %1, %2, %3 }, [ %4 ];"
        : "=r"(r0), "=r"(r1), "=r"(r2), "=r"(r3) : "r"(addr));
}

__device__ __forceinline__ void ldsm_x2t(unsigned int& r0, unsigned int& r1,
                                         unsigned int addr) {
    asm volatile(
        "ldmatrix.sync.aligned.m8n8.x2.trans.shared.b16 { %0, %1 }, [ %2 ];"
        : "=r"(r0), "=r"(r1) : "r"(addr));
}

__device__ __forceinline__ void mma_bf16(float& c0, float& c1, float& c2, float& c3,
                                         unsigned int a0, unsigned int a1,
                                         unsigned int a2, unsigned int a3,
                                         unsigned int b0, unsigned int b1) {
    asm volatile(
        "mma.sync.aligned.m16n8k16.row.col.f32.bf16.bf16.f32 "
        "{ %0, %1, %2, %3 }, { %4, %5, %6, %7 }, { %8, %9 }, { %0, %1, %2, %3 };"
        : "+f"(c0), "+f"(c1), "+f"(c2), "+f"(c3)
        : "r"(a0), "r"(a1), "r"(a2), "r"(a3), "r"(b0), "r"(b1));
}

// ------------------------- init + W2w->bf16 (merged, one launch) ---------------
__global__ void init_all(const float* __restrict__ W) {
    int idx = blockIdx.x * 256 + threadIdx.x;
    if (idx < LL * LL * LL * NB) g_table[idx] = NEGV;
    if (idx < NROW_PAD) g_sum[idx] = 0.f;
    if (idx < (NROW_PAD - NROW) * HD) g_hwb[NROW * HD + idx] = __float2bfloat16(0.f);
    if (idx < LL) g_bar[idx] = 0;
    if (idx < (HD * NV) / 4) {
        int i = idx * 4;
        float4 v = *(const float4*)(W + i);
        __nv_bfloat16 o[4];
        o[0] = __float2bfloat16(v.x);
        o[1] = __float2bfloat16(v.y);
        o[2] = __float2bfloat16(v.z);
        o[3] = __float2bfloat16(v.w);
        *(unsigned long long*)(&g_W2wb[i]) = *(unsigned long long*)o;
    }
}

// ------------------------- enc projections (all 4 in one launch) ---------------
__global__ void proj_gemm(const float* __restrict__ A, const float* __restrict__ W1t,
                          const float* __restrict__ W1w) {
    int which = blockIdx.z;
    const float* W = (which < 2) ? W1t : W1w;
    int koff = (which & 1) * HD;
    float* C = (which == 0) ? g_At : (which == 1) ? g_Bt : (which == 2) ? g_Aw : g_Bw;
    __shared__ float As[16][64];
    __shared__ float Bs[16][64];
    int tid = threadIdx.x;
    int tc = tid & 15, tr = tid >> 4;
    int rb = blockIdx.y * 64, cb = blockIdx.x * 64;
    float acc[4][4];
    for (int i = 0; i < 4; i++)
        for (int q = 0; q < 4; q++) acc[i][q] = 0.f;

    for (int k0 = 0; k0 < HD; k0 += 16) {
        for (int l = tid; l < 1024; l += 256) {
            int r = l >> 4, c = l & 15;
            As[c][r] = A[(rb + r) * HD + k0 + c];
        }
        for (int l = tid; l < 1024; l += 256) {
            int r = l >> 6, c = l & 63;
            Bs[r][c] = W[(koff + k0 + r) * HD + cb + c];
        }
        __syncthreads();
        for (int kk = 0; kk < 16; kk++) {
            float av[4], bv[4];
            for (int i = 0; i < 4; i++) av[i] = As[kk][tr * 4 + i];
            for (int q = 0; q < 4; q++) bv[q] = Bs[kk][tc * 4 + q];
            for (int i = 0; i < 4; i++)
                for (int q = 0; q < 4; q++) acc[i][q] = fmaf(av[i], bv[q], acc[i][q]);
        }
        __syncthreads();
    }
    for (int i = 0; i < 4; i++)
        for (int q = 0; q < 4; q++)
            C[(rb + tr * 4 + i) * HD + cb + tc * 4 + q] = acc[i][q];
}

// ------------------------- per-pair MLP heads -------------------------
__global__ void pair_kernel(const float* __restrict__ b1t, const float* __restrict__ W2t,
                            const float* __restrict__ b2t, const float* __restrict__ b1w) {
    int p = blockIdx.x;
    int i = 0, j = 0;
    if (p < NP) i = inv_pair(p, j);
    int w = threadIdx.x >> 5;
    int lane = threadIdx.x & 31;
    const float* Ar = &g_Aw[(i * NB + w) * HD];
    const float* Br = &g_Bw[(j * NB + w) * HD];
    const float* At = &g_At[(i * NB + w) * HD];
    const float* Bt = &g_Bt[(j * NB + w) * HD];
    __nv_bfloat16* hwrow = &g_hwb[(p * NB + w) * HD];
    float part = 0.f;
    for (int t = 0; t < 16; t++) {
        int h = lane + t * 32;
        float hw = fmaxf(Ar[h] + Br[h] + b1w[h], 0.f);
        hwrow[h] = __float2bfloat16(hw);
        if (p < NP) {
            float ht = fmaxf(At[h] + Bt[h] + b1t[h], 0.f);
            part = fmaf(ht, W2t[h], part);
        }
    }
    if (p < NP) {
        for (int o = 16; o; o >>= 1) part += __shfl_xor_sync(0xffffffffu, part, o);
        if (lane == 0) {
            float z = part + b2t[0];
            float s = 1.f / (1.f + expf(-z));
            g_shlog[p * NB + w] = log1pf(-s + EPSV);
            g_relog[p * NB + w] = logf(s + EPSV);
        }
    }
}

// ------------------------- mma.sync GEMM + sum(exp), cp.async, occ 2 -----------
// C = hwb[16256,512] @ W2wb[512,8192] (bf16 -> f32); per row accumulate
// sum_v exp(c + b2w[v]) into g_sum via atomicAdd (64 column blocks).
// Tiles: BM=128, BN=128, BK=32. 8 warps 2(m) x 4(n); warp tile 64x32
// = 4 (mt, m16) x 4 (nt, n8) mma.m16n8k16 fragments via ldmatrix.
#define AS_LD 40
#define BS_LD 136
__global__ void __launch_bounds__(256, 2) gemm_lse_mma(const float* __restrict__ b2w) {
    __shared__ __align__(128) __nv_bfloat16 As[2][128 * AS_LD];
    __shared__ __align__(128) __nv_bfloat16 Bs[2][32 * BS_LD];
    int tid = threadIdx.x;
    int wid = tid >> 5, lane = tid & 31;
    int wm = wid >> 2, wn = wid & 3;
    int grp = lane >> 2, qt = lane & 3;
    int rowBase = blockIdx.x * 128;
    int v0 = blockIdx.y * 128;

    // cp.async coordinates (A: 512 uint4, B: 512 uint4 -> 2 each/thread)
    int ar0 = tid >> 2, ac0 = (tid & 3) * 8;
    int ar1 = (tid + 256) >> 2, ac1 = ((tid + 256) & 3) * 8;
    int bk0 = tid >> 4, bn0 = (tid & 15) * 8;
    int bk1 = (tid + 256) >> 4, bn1 = ((tid + 256) & 15) * 8;

    float acc[4][4][4];
    for (int mt = 0; mt < 4; mt++)
        for (int nt = 0; nt < 4; nt++)
            for (int e = 0; e < 4; e++) acc[mt][nt][e] = 0.f;

    float bw[4][2];
    for (int nt = 0; nt < 4; nt++) {
        bw[nt][0] = b2w[v0 + wn * 32 + nt * 8 + 2 * qt];
        bw[nt][1] = b2w[v0 + wn * 32 + nt * 8 + 2 * qt + 1];
    }

    unsigned int aBase[2], bBase[2];
    aBase[0] = smem_u32(&As[0][0]);
    aBase[1] = smem_u32(&As[1][0]);
    bBase[0] = smem_u32(&Bs[0][0]);
    bBase[1] = smem_u32(&Bs[1][0]);
    // ldmatrix lane address components
    int am = (lane & 7) + ((lane >> 3) & 1) * 8;   // A row within m16
    int ak = (lane >> 4) * 8;                      // A k offset (8-col halves)
    int bRow = lane & 15;                          // B k-row (x2.trans, 16 addrs)

    // prologue: async-copy k-tile 0 into buffer 0
    __pipeline_memcpy_async(&As[0][ar0 * AS_LD + ac0], &g_hwb[(rowBase + ar0) * HD + ac0], 16);
    __pipeline_memcpy_async(&As[0][ar1 * AS_LD + ac1], &g_hwb[(rowBase + ar1) * HD + ac1], 16);
    __pipeline_memcpy_async(&Bs[0][bk0 * BS_LD + bn0], &g_W2wb[bk0 * NV + v0 + bn0], 16);
    __pipeline_memcpy_async(&Bs[0][bk1 * BS_LD + bn1], &g_W2wb[bk1 * NV + v0 + bn1], 16);
    __pipeline_commit();

    int buf = 0;
    for (int kt = 0; kt < 16; kt++) {
        __syncthreads();   // reads of buf^1 from previous iteration complete
        if (kt + 1 < 16) {
            int k0 = (kt + 1) * 32;
            int nb = buf ^ 1;
            __pipeline_memcpy_async(&As[nb][ar0 * AS_LD + ac0],
                                    &g_hwb[(rowBase + ar0) * HD + k0 + ac0], 16);
            __pipeline_memcpy_async(&As[nb][ar1 * AS_LD + ac1],
                                    &g_hwb[(rowBase + ar1) * HD + k0 + ac1], 16);
            __pipeline_memcpy_async(&Bs[nb][bk0 * BS_LD + bn0],
                                    &g_W2wb[(k0 + bk0) * NV + v0 + bn0], 16);
            __pipeline_memcpy_async(&Bs[nb][bk1 * BS_LD + bn1],
                                    &g_W2wb[(k0 + bk1) * NV + v0 + bn1], 16);
            __pipeline_commit();
            __pipeline_wait_prior(1);
        } else {
            __pipeline_wait_prior(0);
        }
        __syncthreads();   // tile kt visible

        for (int kk = 0; kk < 32; kk += 16) {
            unsigned int afr[4][4];
            for (int mt = 0; mt < 4; mt++) {
                unsigned int aaddr = aBase[buf] +
                    (unsigned int)(((wm * 64 + mt * 16 + am) * AS_LD + kk + ak) * 2);
                ldsm_x4(afr[mt][0], afr[mt][1], afr[mt][2], afr[mt][3], aaddr);
            }
            unsigned int bfr[4][2];
            for (int nt = 0; nt < 4; nt++) {
                unsigned int baddr = bBase[buf] +
                    (unsigned int)(((kk + bRow) * BS_LD + wn * 32 + nt * 8) * 2);
                ldsm_x2t(bfr[nt][0], bfr[nt][1], baddr);
            }
            for (int mt = 0; mt < 4; mt++)
                for (int nt = 0; nt < 4; nt++)
                    mma_bf16(acc[mt][nt][0], acc[mt][nt][1],
                             acc[mt][nt][2], acc[mt][nt][3],
                             afr[mt][0], afr[mt][1], afr[mt][2], afr[mt][3],
                             bfr[nt][0], bfr[nt][1]);
        }
        buf ^= 1;
    }

    // epilogue: exp + quad reduce + atomicAdd (acc rows: grp and grp+8)
    for (int mt = 0; mt < 4; mt++) {
        float s0 = 0.f, s1 = 0.f;
        for (int nt = 0; nt < 4; nt++) {
            s0 += __expf(acc[mt][nt][0] + bw[nt][0]) + __expf(acc[mt][nt][1] + bw[nt][1]);
            s1 += __expf(acc[mt][nt][2] + bw[nt][0]) + __expf(acc[mt][nt][3] + bw[nt][1]);
        }
        s0 += __shfl_xor_sync(0xffffffffu, s0, 1);
        s0 += __shfl_xor_sync(0xffffffffu, s0, 2);
        s1 += __shfl_xor_sync(0xffffffffu, s1, 1);
        s1 += __shfl_xor_sync(0xffffffffu, s1, 2);
        if (qt == 0) {
            int row = rowBase + wm * 64 + mt * 16 + grp;
            atomicAdd(&g_sum[row], s0);
            atomicAdd(&g_sum[row + 8], s1);
        }
    }
}

// ------------------------- gathered word logit + DP base cells (fused) ---------
__global__ void gather_base(const int* __restrict__ sentence,
                            const float* __restrict__ b2w) {
    int row = blockIdx.x * 8 + (threadIdx.x >> 5);
    int lane = threadIdx.x & 31;
    if (row >= NROW) return;
    int p = row >> 3, b = row & 7;
    int jw, i = 0, j = 0;
    if (p < NP) { i = inv_pair(p, j); jw = (j + 1 < LL) ? j + 1 : 0; }
    else jw = 1;
    int word = sentence[jw * NB + b];
    const __nv_bfloat16* hwrow = &g_hwb[(size_t)row * HD];
    float part = 0.f;
    for (int tt = 0; tt < 16; tt++) {
        int h = lane + tt * 32;
        part = fmaf(__bfloat162float(hwrow[h]),
                    __bfloat162float(g_W2wb[(size_t)h * NV + word]), part);
    }
    for (int o = 16; o; o >>= 1) part += __shfl_xor_sync(0xffffffffu, part, o);
    if (lane == 0) {
        float gw = part + b2w[word];
        float lse = logf(g_sum[row]);
        if (p < NP) {
            if (j <= LL - 2)
                g_table[((i * LL + j) * LL + (j + 1)) * NB + b] =
                    g_shlog[row] + gw - lse;
        } else {
            g_table[(0 * LL + 1) * NB + b] = gw - lse;
        }
    }
}

// ------------------------- full inside recursion, one persistent launch --------
__global__ void dp_all(float* __restrict__ out) {
    int blk = blockIdx.x;
    int tid = threadIdx.x;
    __shared__ float right[62 * 8];
    for (int gap = 2; gap <= LL - 1; gap++) {
        int nblk = LL - gap;
        if (blk < nblk) {
            int iv = blk;
            int jv = iv + gap;
            int nk = gap - 1;
            for (int m = tid; m < nk * 8; m += 512) {
                int d = m >> 3, b = m & 7;
                int k = iv + 1 + d;
                right[m] = g_table[((iv * LL + k) * LL + jv) * NB + b] +
                           g_relog[pidx(k, jv) * NB + b];
            }
            __syncthreads();
            int b = tid & 7, l = tid >> 3;
            const float* base = &g_table[(l * LL + iv) * LL * NB + b];
            float mx = -3.0e38f, s = 0.f;
            for (int d = 0; d < nk; d++) {
                int k = iv + 1 + d;
                float x = base[k * NB] + right[d * 8 + b];
                if (x > mx) { s = s * __expf(mx - x) + 1.f; mx = x; }
                else s += __expf(x - mx);
            }
            g_table[((l * LL + iv) * LL + jv) * NB + b] = mx + logf(s);
            __syncthreads();
        }
        if (tid == 0) {
            __threadfence();
            atomicAdd(&g_bar[gap], 1);
            while (*((volatile int*)&g_bar[gap]) < (int)gridDim.x) {}
            __threadfence();
        }
        __syncthreads();
    }
    if (blk == 0 && tid < NB)
        out[tid] = g_table[(0 * LL + (LL - 1)) * NB + tid];
}

// ------------------------- launch -------------------------
extern "C" void kernel_launch(void* const* d_in, const int* in_sizes, int n_in,
                              void* d_out, int out_size) {
    const float* enc = (const float*)d_in[0];
    const int* sentence = (const int*)d_in[1];
    const float* W1t = (const float*)d_in[2];
    const float* b1t = (const float*)d_in[3];
    const float* W2t = (const float*)d_in[4];
    const float* b2t = (const float*)d_in[5];
    const float* W1w = (const float*)d_in[6];
    const float* b1w = (const float*)d_in[7];
    const float* W2w = (const float*)d_in[8];
    const float* b2w = (const float*)d_in[9];
    float* out = (float*)d_out;

    init_all<<<8192, 256>>>(W2w);                       // launch 1
    proj_gemm<<<dim3(8, 8, 4), 256>>>(enc, W1t, W1w);   // launch 2
    pair_kernel<<<NP + 1, 256>>>(b1t, W2t, b2t, b1w);   // launch 3
    gemm_lse_mma<<<dim3(127, 64), 256>>>(b2w);          // launch 4 (ncu target)
    gather_base<<<(NROW + 7) / 8, 256>>>(sentence, b2w);
    dp_all<<<62, 512>>>(out);
}

// round 12
// speedup vs baseline: 1.4747x; 1.0578x over previous
#include <cuda_runtime.h>
#include <cuda_bf16.h>
#include <cuda_pipeline.h>
#include <math.h>

#define LL 64
#define NB 8
#define HD 512
#define NV 8192
#define NP 2016                       // L*(L-1)/2 pairs
#define NROW ((NP + 1) * NB)          // 16136 rows (pairs + the (0,0) cell)
#define NROW_PAD (127 * 128)          // 16256, padded to GEMM row tiles
#define NEGV (-1e9f)
#define EPSV 4.5399929762484854e-05f  // exp(-10)

// ------------------------- device scratch -------------------------
__device__ float g_At[LL * NB * HD];
__device__ float g_Bt[LL * NB * HD];
__device__ float g_Aw[LL * NB * HD];
__device__ float g_Bw[LL * NB * HD];
__device__ __nv_bfloat16 g_hwb[NROW_PAD * HD];   // relu hidden (bf16)
__device__ __nv_bfloat16 g_W2wb[HD * NV];        // W2w in bf16, k-major [k][v]
__device__ float g_shlog[NP * NB];
__device__ float g_relog[NP * NB];
__device__ float g_sum[NROW_PAD];
__device__ float g_table[LL * LL * LL * NB];
__device__ int g_bar[LL];

__device__ __forceinline__ int pidx(int i, int j) {
    return i * (2 * LL - 1 - i) / 2 + (j - i - 1);
}

__device__ __forceinline__ int inv_pair(int p, int& j) {
    int i = 0;
    while (p >= (LL - 1 - i)) { p -= (LL - 1 - i); i++; }
    j = i + 1 + p;
    return i;
}

// ------------------------- sanitized PTX helpers (no Jinja-active tokens) ------
__device__ __forceinline__ unsigned int smem_u32(const void* p) {
    unsigned int a;
    asm("{ .reg .u64 t; cvta.to.shared.u64 t, %1; cvt.u32.u64 %0, t; }"
        : "=r"(a) : "l"(p));
    return a;
}

__device__ __forceinline__ void ldsm_x4(unsigned int& r0, unsigned int& r1,
                                        unsigned int& r2, unsigned int& r3,
                                        unsigned int addr) {
    asm volatile(
        "ldmatrix.sync.aligned.m8n8.x4.shared.b16 { %0, %1, %2, %3 }, [ %4 ];"
        : "=r"(r0), "=r"(r1), "=r"(r2), "=r"(r3) : "r"(addr));
}

__device__ __forceinline__ void ldsm_x2t(unsigned int& r0, unsigned int& r1,
                                         unsigned int addr) {
    asm volatile(
        "ldmatrix.sync.aligned.m8n8.x2.trans.shared.b16 { %0, %1 }, [ %2 ];"
        : "=r"(r0), "=r"(r1) : "r"(addr));
}

__device__ __forceinline__ void mma_bf16(float& c0, float& c1, float& c2, float& c3,
                                         unsigned int a0, unsigned int a1,
                                         unsigned int a2, unsigned int a3,
                                         unsigned int b0, unsigned int b1) {
    asm volatile(
        "mma.sync.aligned.m16n8k16.row.col.f32.bf16.bf16.f32 "
        "{ %0, %1, %2, %3 }, { %4, %5, %6, %7 }, { %8, %9 }, { %0, %1, %2, %3 };"
        : "+f"(c0), "+f"(c1), "+f"(c2), "+f"(c3)
        : "r"(a0), "r"(a1), "r"(a2), "r"(a3), "r"(b0), "r"(b1));
}

// ------------------------- init + W2w->bf16 (merged, one launch) ---------------
__global__ void init_all(const float* __restrict__ W) {
    int idx = blockIdx.x * 256 + threadIdx.x;
    if (idx < (LL * LL * LL * NB) / 4) {
        float4 v4 = make_float4(NEGV, NEGV, NEGV, NEGV);
        *(float4*)(&g_table[idx * 4]) = v4;
    }
    if (idx < NROW_PAD / 4)
        *(float4*)(&g_sum[idx * 4]) = make_float4(0.f, 0.f, 0.f, 0.f);
    if (idx < ((NROW_PAD - NROW) * HD) / 4) {
        __nv_bfloat16 z = __float2bfloat16(0.f);
        __nv_bfloat16 o[4] = {z, z, z, z};
        *(unsigned long long*)(&g_hwb[NROW * HD + idx * 4]) = *(unsigned long long*)o;
    }
    if (idx < LL) g_bar[idx] = 0;
    if (idx < (HD * NV) / 4) {
        int i = idx * 4;
        float4 v = *(const float4*)(W + i);
        __nv_bfloat16 o[4];
        o[0] = __float2bfloat16(v.x);
        o[1] = __float2bfloat16(v.y);
        o[2] = __float2bfloat16(v.z);
        o[3] = __float2bfloat16(v.w);
        *(unsigned long long*)(&g_W2wb[i]) = *(unsigned long long*)o;
    }
}

// ------------------------- enc projections (all 4 in one launch) ---------------
__global__ void proj_gemm(const float* __restrict__ A, const float* __restrict__ W1t,
                          const float* __restrict__ W1w) {
    int which = blockIdx.z;
    const float* W = (which < 2) ? W1t : W1w;
    int koff = (which & 1) * HD;
    float* C = (which == 0) ? g_At : (which == 1) ? g_Bt : (which == 2) ? g_Aw : g_Bw;
    __shared__ float As[16][64];
    __shared__ float Bs[16][64];
    int tid = threadIdx.x;
    int tc = tid & 15, tr = tid >> 4;
    int rb = blockIdx.y * 64, cb = blockIdx.x * 64;
    float acc[4][4];
    for (int i = 0; i < 4; i++)
        for (int q = 0; q < 4; q++) acc[i][q] = 0.f;

    for (int k0 = 0; k0 < HD; k0 += 16) {
        for (int l = tid; l < 1024; l += 256) {
            int r = l >> 4, c = l & 15;
            As[c][r] = A[(rb + r) * HD + k0 + c];
        }
        for (int l = tid; l < 1024; l += 256) {
            int r = l >> 6, c = l & 63;
            Bs[r][c] = W[(koff + k0 + r) * HD + cb + c];
        }
        __syncthreads();
        for (int kk = 0; kk < 16; kk++) {
            float av[4], bv[4];
            for (int i = 0; i < 4; i++) av[i] = As[kk][tr * 4 + i];
            for (int q = 0; q < 4; q++) bv[q] = Bs[kk][tc * 4 + q];
            for (int i = 0; i < 4; i++)
                for (int q = 0; q < 4; q++) acc[i][q] = fmaf(av[i], bv[q], acc[i][q]);
        }
        __syncthreads();
    }
    for (int i = 0; i < 4; i++)
        for (int q = 0; q < 4; q++)
            C[(rb + tr * 4 + i) * HD + cb + tc * 4 + q] = acc[i][q];
}

// ------------------------- per-pair MLP heads -------------------------
__global__ void pair_kernel(const float* __restrict__ b1t, const float* __restrict__ W2t,
                            const float* __restrict__ b2t, const float* __restrict__ b1w) {
    int p = blockIdx.x;
    int i = 0, j = 0;
    if (p < NP) i = inv_pair(p, j);
    int w = threadIdx.x >> 5;
    int lane = threadIdx.x & 31;
    const float* Ar = &g_Aw[(i * NB + w) * HD];
    const float* Br = &g_Bw[(j * NB + w) * HD];
    const float* At = &g_At[(i * NB + w) * HD];
    const float* Bt = &g_Bt[(j * NB + w) * HD];
    __nv_bfloat16* hwrow = &g_hwb[(p * NB + w) * HD];
    float part = 0.f;
    for (int t = 0; t < 16; t++) {
        int h = lane + t * 32;
        float hw = fmaxf(Ar[h] + Br[h] + b1w[h], 0.f);
        hwrow[h] = __float2bfloat16(hw);
        if (p < NP) {
            float ht = fmaxf(At[h] + Bt[h] + b1t[h], 0.f);
            part = fmaf(ht, W2t[h], part);
        }
    }
    if (p < NP) {
        for (int o = 16; o; o >>= 1) part += __shfl_xor_sync(0xffffffffu, part, o);
        if (lane == 0) {
            float z = part + b2t[0];
            float s = 1.f / (1.f + expf(-z));
            g_shlog[p * NB + w] = log1pf(-s + EPSV);
            g_relog[p * NB + w] = logf(s + EPSV);
        }
    }
}

// ------------------------- mma.sync GEMM + sum(exp) ----------------------------
// 3-stage cp.async ring (one __syncthreads per k-tile), XOR-swizzled B tile
// (conflict-free ldmatrix.trans), BM=128 BN=128 BK=32, warp tile 64x32, occ 2.
#define AS_LD 40
#define A_BYTES (128 * AS_LD * 2)          // 10240
#define B_BYTES (32 * 128 * 2)             // 8192
#define STAGE_BYTES (A_BYTES + B_BYTES)    // 18432
#define SMEM_GEMM (3 * STAGE_BYTES)        // 55296
__global__ void __launch_bounds__(256, 2) gemm_lse_mma(const float* __restrict__ b2w) {
    extern __shared__ __align__(128) char smem[];
    int tid = threadIdx.x;
    int wid = tid >> 5, lane = tid & 31;
    int wm = wid >> 2, wn = wid & 3;
    int grp = lane >> 2, qt = lane & 3;
    int rowBase = blockIdx.x * 128;
    int v0 = blockIdx.y * 128;

    unsigned int aBase[3], bBase[3];
    for (int s = 0; s < 3; s++) {
        aBase[s] = smem_u32(smem + s * STAGE_BYTES);
        bBase[s] = aBase[s] + A_BYTES;
    }

    // cp.async coordinates
    int ar0 = tid >> 2, ac0 = (tid & 3) * 8;   // A rows ar0, ar0+64 same col
    int bk0 = tid >> 4, bc0 = tid & 15;        // B rows bk0, bk0+16 same chunk

    float acc[4][4][4];
    for (int mt = 0; mt < 4; mt++)
        for (int nt = 0; nt < 4; nt++)
            for (int e = 0; e < 4; e++) acc[mt][nt][e] = 0.f;

    // ldmatrix lane address components
    int am = (lane & 7) + ((lane >> 3) & 1) * 8;   // A row within m16
    int ak = (lane >> 4) * 8;                      // A k offset (8-col halves)
    int bRow = lane & 15;                          // B k-row (x2.trans)

    // prologue: stage k-tiles 0 and 1
    for (int pf = 0; pf < 2; pf++) {
        char* as = smem + pf * STAGE_BYTES;
        char* bs = as + A_BYTES;
        int k0 = pf * 32;
        __pipeline_memcpy_async(as + (ar0 * AS_LD + ac0) * 2,
                                &g_hwb[(rowBase + ar0) * HD + k0 + ac0], 16);
        __pipeline_memcpy_async(as + ((ar0 + 64) * AS_LD + ac0) * 2,
                                &g_hwb[(rowBase + ar0 + 64) * HD + k0 + ac0], 16);
        __pipeline_memcpy_async(bs + (bk0 * 128 + ((bc0 ^ (bk0 & 7)) * 8)) * 2,
                                &g_W2wb[(k0 + bk0) * NV + v0 + bc0 * 8], 16);
        __pipeline_memcpy_async(bs + ((bk0 + 16) * 128 + ((bc0 ^ ((bk0 + 16) & 7)) * 8)) * 2,
                                &g_W2wb[(k0 + bk0 + 16) * NV + v0 + bc0 * 8], 16);
        __pipeline_commit();
    }

    for (int kt = 0; kt < 16; kt++) {
        if (kt < 15) __pipeline_wait_prior(1);   // tile kt resident
        else __pipeline_wait_prior(0);
        __syncthreads();                          // visible to all; prev stage free

        if (kt + 2 < 16) {
            int st = (kt + 2) % 3;
            char* as = smem + st * STAGE_BYTES;
            char* bs = as + A_BYTES;
            int k0 = (kt + 2) * 32;
            __pipeline_memcpy_async(as + (ar0 * AS_LD + ac0) * 2,
                                    &g_hwb[(rowBase + ar0) * HD + k0 + ac0], 16);
            __pipeline_memcpy_async(as + ((ar0 + 64) * AS_LD + ac0) * 2,
                                    &g_hwb[(rowBase + ar0 + 64) * HD + k0 + ac0], 16);
            __pipeline_memcpy_async(bs + (bk0 * 128 + ((bc0 ^ (bk0 & 7)) * 8)) * 2,
                                    &g_W2wb[(k0 + bk0) * NV + v0 + bc0 * 8], 16);
            __pipeline_memcpy_async(bs + ((bk0 + 16) * 128 + ((bc0 ^ ((bk0 + 16) & 7)) * 8)) * 2,
                                    &g_W2wb[(k0 + bk0 + 16) * NV + v0 + bc0 * 8], 16);
            __pipeline_commit();
        }

        int st = kt % 3;
        for (int kk = 0; kk < 32; kk += 16) {
            unsigned int afr[4][4];
            for (int mt = 0; mt < 4; mt++) {
                unsigned int aaddr = aBase[st] +
                    (unsigned int)(((wm * 64 + mt * 16 + am) * AS_LD + kk + ak) * 2);
                ldsm_x4(afr[mt][0], afr[mt][1], afr[mt][2], afr[mt][3], aaddr);
            }
            unsigned int bfr[4][2];
            int br = kk + bRow;
            for (int nt = 0; nt < 4; nt++) {
                int chunk = (wn * 4 + nt) ^ (br & 7);
                unsigned int baddr = bBase[st] +
                    (unsigned int)((br * 128 + chunk * 8) * 2);
                ldsm_x2t(bfr[nt][0], bfr[nt][1], baddr);
            }
            for (int mt = 0; mt < 4; mt++)
                for (int nt = 0; nt < 4; nt++)
                    mma_bf16(acc[mt][nt][0], acc[mt][nt][1],
                             acc[mt][nt][2], acc[mt][nt][3],
                             afr[mt][0], afr[mt][1], afr[mt][2], afr[mt][3],
                             bfr[nt][0], bfr[nt][1]);
        }
    }

    // epilogue: exp + quad reduce + atomicAdd (acc rows: grp and grp+8)
    float bw[4][2];
    for (int nt = 0; nt < 4; nt++) {
        bw[nt][0] = b2w[v0 + wn * 32 + nt * 8 + 2 * qt];
        bw[nt][1] = b2w[v0 + wn * 32 + nt * 8 + 2 * qt + 1];
    }
    for (int mt = 0; mt < 4; mt++) {
        float s0 = 0.f, s1 = 0.f;
        for (int nt = 0; nt < 4; nt++) {
            s0 += __expf(acc[mt][nt][0] + bw[nt][0]) + __expf(acc[mt][nt][1] + bw[nt][1]);
            s1 += __expf(acc[mt][nt][2] + bw[nt][0]) + __expf(acc[mt][nt][3] + bw[nt][1]);
        }
        s0 += __shfl_xor_sync(0xffffffffu, s0, 1);
        s0 += __shfl_xor_sync(0xffffffffu, s0, 2);
        s1 += __shfl_xor_sync(0xffffffffu, s1, 1);
        s1 += __shfl_xor_sync(0xffffffffu, s1, 2);
        if (qt == 0) {
            int row = rowBase + wm * 64 + mt * 16 + grp;
            atomicAdd(&g_sum[row], s0);
            atomicAdd(&g_sum[row + 8], s1);
        }
    }
}

// ------------------------- gathered word logit + DP base cells (fused) ---------
__global__ void gather_base(const int* __restrict__ sentence,
                            const float* __restrict__ b2w) {
    int row = blockIdx.x * 8 + (threadIdx.x >> 5);
    int lane = threadIdx.x & 31;
    if (row >= NROW) return;
    int p = row >> 3, b = row & 7;
    int jw, i = 0, j = 0;
    if (p < NP) { i = inv_pair(p, j); jw = (j + 1 < LL) ? j + 1 : 0; }
    else jw = 1;
    int word = sentence[jw * NB + b];
    const __nv_bfloat16* hwrow = &g_hwb[(size_t)row * HD];
    float part = 0.f;
    for (int tt = 0; tt < 16; tt++) {
        int h = lane + tt * 32;
        part = fmaf(__bfloat162float(hwrow[h]),
                    __bfloat162float(g_W2wb[(size_t)h * NV + word]), part);
    }
    for (int o = 16; o; o >>= 1) part += __shfl_xor_sync(0xffffffffu, part, o);
    if (lane == 0) {
        float gw = part + b2w[word];
        float lse = logf(g_sum[row]);
        if (p < NP) {
            if (j <= LL - 2)
                g_table[((i * LL + j) * LL + (j + 1)) * NB + b] =
                    g_shlog[row] + gw - lse;
        } else {
            g_table[(0 * LL + 1) * NB + b] = gw - lse;
        }
    }
}

// ------------------------- full inside recursion, one persistent launch --------
__global__ void dp_all(float* __restrict__ out) {
    int blk = blockIdx.x;
    int tid = threadIdx.x;
    __shared__ float right[62 * 8];
    for (int gap = 2; gap <= LL - 1; gap++) {
        int nblk = LL - gap;
        if (blk < nblk) {
            int iv = blk;
            int jv = iv + gap;
            int nk = gap - 1;
            for (int m = tid; m < nk * 8; m += 512) {
                int d = m >> 3, b = m & 7;
                int k = iv + 1 + d;
                right[m] = g_table[((iv * LL + k) * LL + jv) * NB + b] +
                           g_relog[pidx(k, jv) * NB + b];
            }
            __syncthreads();
            int b = tid & 7, l = tid >> 3;
            const float* base = &g_table[(l * LL + iv) * LL * NB + b];
            float mx = -3.0e38f, s = 0.f;
            for (int d = 0; d < nk; d++) {
                int k = iv + 1 + d;
                float x = base[k * NB] + right[d * 8 + b];
                if (x > mx) { s = s * __expf(mx - x) + 1.f; mx = x; }
                else s += __expf(x - mx);
            }
            g_table[((l * LL + iv) * LL + jv) * NB + b] = mx + logf(s);
            __syncthreads();
        }
        if (tid == 0) {
            __threadfence();
            atomicAdd(&g_bar[gap], 1);
            while (*((volatile int*)&g_bar[gap]) < (int)gridDim.x) {}
            __threadfence();
        }
        __syncthreads();
    }
    if (blk == 0 && tid < NB)
        out[tid] = g_table[(0 * LL + (LL - 1)) * NB + tid];
}

// ------------------------- launch -------------------------
extern "C" void kernel_launch(void* const* d_in, const int* in_sizes, int n_in,
                              void* d_out, int out_size) {
    const float* enc = (const float*)d_in[0];
    const int* sentence = (const int*)d_in[1];
    const float* W1t = (const float*)d_in[2];
    const float* b1t = (const float*)d_in[3];
    const float* W2t = (const float*)d_in[4];
    const float* b2t = (const float*)d_in[5];
    const float* W1w = (const float*)d_in[6];
    const float* b1w = (const float*)d_in[7];
    const float* W2w = (const float*)d_in[8];
    const float* b2w = (const float*)d_in[9];
    float* out = (float*)d_out;

    cudaFuncSetAttribute(gemm_lse_mma, cudaFuncAttributeMaxDynamicSharedMemorySize,
                         SMEM_GEMM);

    init_all<<<4096, 256>>>(W2w);                          // launch 1
    proj_gemm<<<dim3(8, 8, 4), 256>>>(enc, W1t, W1w);      // launch 2
    pair_kernel<<<NP + 1, 256>>>(b1t, W2t, b2t, b1w);      // launch 3
    gemm_lse_mma<<<dim3(127, 64), 256, SMEM_GEMM>>>(b2w);  // launch 4 (ncu target)
    gather_base<<<(NROW + 7) / 8, 256>>>(sentence, b2w);
    dp_all<<<62, 512>>>(out);
}

// round 13
// speedup vs baseline: 1.5615x; 1.0588x over previous
#include <cuda_runtime.h>
#include <cuda_bf16.h>
#include <cuda_pipeline.h>
#include <math.h>

#define LL 64
#define NB 8
#define HD 512
#define NV 8192
#define NP 2016                       // L*(L-1)/2 pairs
#define NROW ((NP + 1) * NB)          // 16136 rows (pairs + the (0,0) cell)
#define NROW_PAD (127 * 128)          // 16256, padded to GEMM row tiles
#define NEGV (-1e9f)
#define EPSV 4.5399929762484854e-05f  // exp(-10)

// ------------------------- device scratch -------------------------
__device__ float g_At[LL * NB * HD];
__device__ float g_Bt[LL * NB * HD];
__device__ float g_Aw[LL * NB * HD];
__device__ float g_Bw[LL * NB * HD];
__device__ __nv_bfloat16 g_encb[LL * NB * HD];   // enc in bf16
__device__ __nv_bfloat16 g_W1tb[2 * HD * HD];    // W1t in bf16
__device__ __nv_bfloat16 g_W1wb[2 * HD * HD];    // W1w in bf16
__device__ __nv_bfloat16 g_hwb[NROW_PAD * HD];   // relu hidden (bf16)
__device__ __nv_bfloat16 g_W2wb[HD * NV];        // W2w in bf16, k-major [k][v]
__device__ float g_shlog[NP * NB];
__device__ float g_relog[NP * NB];
__device__ float g_sum[NROW_PAD];
__device__ float g_table[LL * LL * LL * NB];
__device__ int g_bar[LL];

__device__ __forceinline__ int pidx(int i, int j) {
    return i * (2 * LL - 1 - i) / 2 + (j - i - 1);
}

__device__ __forceinline__ int inv_pair(int p, int& j) {
    int i = 0;
    while (p >= (LL - 1 - i)) { p -= (LL - 1 - i); i++; }
    j = i + 1 + p;
    return i;
}

// ------------------------- sanitized PTX helpers (no Jinja-active tokens) ------
__device__ __forceinline__ unsigned int smem_u32(const void* p) {
    unsigned int a;
    asm("{ .reg .u64 t; cvta.to.shared.u64 t, %1; cvt.u32.u64 %0, t; }"
        : "=r"(a) : "l"(p));
    return a;
}

__device__ __forceinline__ void ldsm_x4(unsigned int& r0, unsigned int& r1,
                                        unsigned int& r2, unsigned int& r3,
                                        unsigned int addr) {
    asm volatile(
        "ldmatrix.sync.aligned.m8n8.x4.shared.b16 { %0, %1, %2, %3 }, [ %4 ];"
        : "=r"(r0), "=r"(r1), "=r"(r2), "=r"(r3) : "r"(addr));
}

__device__ __forceinline__ void ldsm_x4t(unsigned int& r0, unsigned int& r1,
                                         unsigned int& r2, unsigned int& r3,
                                         unsigned int addr) {
    asm volatile(
        "ldmatrix.sync.aligned.m8n8.x4.trans.shared.b16 { %0, %1, %2, %3 }, [ %4 ];"
        : "=r"(r0), "=r"(r1), "=r"(r2), "=r"(r3) : "r"(addr));
}

__device__ __forceinline__ void mma_bf16(float& c0, float& c1, float& c2, float& c3,
                                         unsigned int a0, unsigned int a1,
                                         unsigned int a2, unsigned int a3,
                                         unsigned int b0, unsigned int b1) {
    asm volatile(
        "mma.sync.aligned.m16n8k16.row.col.f32.bf16.bf16.f32 "
        "{ %0, %1, %2, %3 }, { %4, %5, %6, %7 }, { %8, %9 }, { %0, %1, %2, %3 };"
        : "+f"(c0), "+f"(c1), "+f"(c2), "+f"(c3)
        : "r"(a0), "r"(a1), "r"(a2), "r"(a3), "r"(b0), "r"(b1));
}

// ------------------------- init + conversions (one launch) ---------------------
__global__ void init_all(const float* __restrict__ W, const float* __restrict__ enc,
                         const float* __restrict__ W1t, const float* __restrict__ W1w) {
    int idx = blockIdx.x * 256 + threadIdx.x;
    if (idx < (LL * LL * LL * NB) / 4) {
        float4 v4 = make_float4(NEGV, NEGV, NEGV, NEGV);
        *(float4*)(&g_table[idx * 4]) = v4;
    }
    if (idx < NROW_PAD / 4)
        *(float4*)(&g_sum[idx * 4]) = make_float4(0.f, 0.f, 0.f, 0.f);
    if (idx < ((NROW_PAD - NROW) * HD) / 4) {
        __nv_bfloat16 z = __float2bfloat16(0.f);
        __nv_bfloat16 o[4] = {z, z, z, z};
        *(unsigned long long*)(&g_hwb[NROW * HD + idx * 4]) = *(unsigned long long*)o;
    }
    if (idx < LL) g_bar[idx] = 0;
    if (idx < (HD * NV) / 4) {
        int i = idx * 4;
        float4 v = *(const float4*)(W + i);
        __nv_bfloat16 o[4];
        o[0] = __float2bfloat16(v.x);
        o[1] = __float2bfloat16(v.y);
        o[2] = __float2bfloat16(v.z);
        o[3] = __float2bfloat16(v.w);
        *(unsigned long long*)(&g_W2wb[i]) = *(unsigned long long*)o;
    }
    if (idx < (LL * NB * HD) / 4) {
        int i = idx * 4;
        float4 v = *(const float4*)(enc + i);
        __nv_bfloat16 o[4];
        o[0] = __float2bfloat16(v.x);
        o[1] = __float2bfloat16(v.y);
        o[2] = __float2bfloat16(v.z);
        o[3] = __float2bfloat16(v.w);
        *(unsigned long long*)(&g_encb[i]) = *(unsigned long long*)o;
    }
    if (idx < (2 * HD * HD) / 4) {
        int i = idx * 4;
        float4 v = *(const float4*)(W1t + i);
        __nv_bfloat16 o[4];
        o[0] = __float2bfloat16(v.x);
        o[1] = __float2bfloat16(v.y);
        o[2] = __float2bfloat16(v.z);
        o[3] = __float2bfloat16(v.w);
        *(unsigned long long*)(&g_W1tb[i]) = *(unsigned long long*)o;
        float4 w = *(const float4*)(W1w + i);
        o[0] = __float2bfloat16(w.x);
        o[1] = __float2bfloat16(w.y);
        o[2] = __float2bfloat16(w.z);
        o[3] = __float2bfloat16(w.w);
        *(unsigned long long*)(&g_W1wb[i]) = *(unsigned long long*)o;
    }
}

// ------------------------- shared GEMM tile constants --------------------------
#define AS_LD 40
#define A_BYTES (128 * AS_LD * 2)          // 10240
#define B_BYTES (32 * 128 * 2)             // 8192
#define STAGE_BYTES (A_BYTES + B_BYTES)    // 18432
#define SMEM_GEMM (3 * STAGE_BYTES)        // 55296

// ------------------------- enc projections via mma (all 4, one launch) ---------
// C[512,512] = encb[512,512] @ W1b[koff:+512, :] (bf16 -> fp32 out).
// Same 3-stage cp.async ring / swizzled-B structure as gemm_lse_mma; K=512.
__global__ void __launch_bounds__(256, 2) proj_mma(int dummy) {
    extern __shared__ __align__(128) char smem[];
    int which = blockIdx.z;
    const __nv_bfloat16* W = (which < 2) ? g_W1tb : g_W1wb;
    int koff = (which & 1) * HD;
    float* C = (which == 0) ? g_At : (which == 1) ? g_Bt : (which == 2) ? g_Aw : g_Bw;

    int tid = threadIdx.x;
    int wid = tid >> 5, lane = tid & 31;
    int wm = wid >> 2, wn = wid & 3;
    int grp = lane >> 2, qt = lane & 3;
    int rowBase = blockIdx.y * 128;
    int cb = blockIdx.x * 128;

    unsigned int aBase[3], bBase[3];
    for (int s = 0; s < 3; s++) {
        aBase[s] = smem_u32(smem + s * STAGE_BYTES);
        bBase[s] = aBase[s] + A_BYTES;
    }
    int ar0 = tid >> 2, ac0 = (tid & 3) * 8;
    int bk0 = tid >> 4, bc0 = tid & 15;

    float acc[4][4][4];
    for (int mt = 0; mt < 4; mt++)
        for (int nt = 0; nt < 4; nt++)
            for (int e = 0; e < 4; e++) acc[mt][nt][e] = 0.f;

    int am = (lane & 7) + ((lane >> 3) & 1) * 8;
    int ak = (lane >> 4) * 8;
    int bRow = lane & 15;
    int bMat = lane >> 4;   // 0/1: which n-chunk within an x4.trans

    for (int pf = 0; pf < 2; pf++) {
        char* as = smem + pf * STAGE_BYTES;
        char* bs = as + A_BYTES;
        int k0 = pf * 32;
        __pipeline_memcpy_async(as + (ar0 * AS_LD + ac0) * 2,
                                &g_encb[(rowBase + ar0) * HD + k0 + ac0], 16);
        __pipeline_memcpy_async(as + ((ar0 + 64) * AS_LD + ac0) * 2,
                                &g_encb[(rowBase + ar0 + 64) * HD + k0 + ac0], 16);
        __pipeline_memcpy_async(bs + (bk0 * 128 + ((bc0 ^ (bk0 & 7)) * 8)) * 2,
                                &W[(koff + k0 + bk0) * HD + cb + bc0 * 8], 16);
        __pipeline_memcpy_async(bs + ((bk0 + 16) * 128 + ((bc0 ^ ((bk0 + 16) & 7)) * 8)) * 2,
                                &W[(koff + k0 + bk0 + 16) * HD + cb + bc0 * 8], 16);
        __pipeline_commit();
    }

    for (int kt = 0; kt < 16; kt++) {
        if (kt < 15) __pipeline_wait_prior(1);
        else __pipeline_wait_prior(0);
        __syncthreads();
        if (kt + 2 < 16) {
            int st = (kt + 2) % 3;
            char* as = smem + st * STAGE_BYTES;
            char* bs = as + A_BYTES;
            int k0 = (kt + 2) * 32;
            __pipeline_memcpy_async(as + (ar0 * AS_LD + ac0) * 2,
                                    &g_encb[(rowBase + ar0) * HD + k0 + ac0], 16);
            __pipeline_memcpy_async(as + ((ar0 + 64) * AS_LD + ac0) * 2,
                                    &g_encb[(rowBase + ar0 + 64) * HD + k0 + ac0], 16);
            __pipeline_memcpy_async(bs + (bk0 * 128 + ((bc0 ^ (bk0 & 7)) * 8)) * 2,
                                    &W[(koff + k0 + bk0) * HD + cb + bc0 * 8], 16);
            __pipeline_memcpy_async(bs + ((bk0 + 16) * 128 + ((bc0 ^ ((bk0 + 16) & 7)) * 8)) * 2,
                                    &W[(koff + k0 + bk0 + 16) * HD + cb + bc0 * 8], 16);
            __pipeline_commit();
        }
        int st = kt % 3;
        for (int kk = 0; kk < 32; kk += 16) {
            unsigned int afr[4][4];
            for (int mt = 0; mt < 4; mt++) {
                unsigned int aaddr = aBase[st] +
                    (unsigned int)(((wm * 64 + mt * 16 + am) * AS_LD + kk + ak) * 2);
                ldsm_x4(afr[mt][0], afr[mt][1], afr[mt][2], afr[mt][3], aaddr);
            }
            unsigned int bfr[4][2];
            int br = kk + bRow;
            for (int nb2 = 0; nb2 < 2; nb2++) {
                int ntx = nb2 * 2 + bMat;
                int chunk = (wn * 4 + ntx) ^ (br & 7);
                unsigned int baddr = bBase[st] +
                    (unsigned int)((br * 128 + chunk * 8) * 2);
                ldsm_x4t(bfr[nb2 * 2][0], bfr[nb2 * 2][1],
                         bfr[nb2 * 2 + 1][0], bfr[nb2 * 2 + 1][1], baddr);
            }
            for (int mt = 0; mt < 4; mt++)
                for (int nt = 0; nt < 4; nt++)
                    mma_bf16(acc[mt][nt][0], acc[mt][nt][1],
                             acc[mt][nt][2], acc[mt][nt][3],
                             afr[mt][0], afr[mt][1], afr[mt][2], afr[mt][3],
                             bfr[nt][0], bfr[nt][1]);
        }
    }

    // epilogue: direct fp32 store (rows grp, grp+8 per fragment)
    for (int mt = 0; mt < 4; mt++)
        for (int nt = 0; nt < 4; nt++) {
            int m0 = rowBase + wm * 64 + mt * 16 + grp;
            int c0 = cb + wn * 32 + nt * 8 + 2 * qt;
            *(float2*)(&C[m0 * HD + c0]) = make_float2(acc[mt][nt][0], acc[mt][nt][1]);
            *(float2*)(&C[(m0 + 8) * HD + c0]) = make_float2(acc[mt][nt][2], acc[mt][nt][3]);
        }
}

// ------------------------- per-pair MLP heads -------------------------
__global__ void pair_kernel(const float* __restrict__ b1t, const float* __restrict__ W2t,
                            const float* __restrict__ b2t, const float* __restrict__ b1w) {
    int p = blockIdx.x;
    int i = 0, j = 0;
    if (p < NP) i = inv_pair(p, j);
    int w = threadIdx.x >> 5;
    int lane = threadIdx.x & 31;
    const float* Ar = &g_Aw[(i * NB + w) * HD];
    const float* Br = &g_Bw[(j * NB + w) * HD];
    const float* At = &g_At[(i * NB + w) * HD];
    const float* Bt = &g_Bt[(j * NB + w) * HD];
    __nv_bfloat16* hwrow = &g_hwb[(p * NB + w) * HD];
    float part = 0.f;
    for (int t = 0; t < 16; t++) {
        int h = lane + t * 32;
        float hw = fmaxf(Ar[h] + Br[h] + b1w[h], 0.f);
        hwrow[h] = __float2bfloat16(hw);
        if (p < NP) {
            float ht = fmaxf(At[h] + Bt[h] + b1t[h], 0.f);
            part = fmaf(ht, W2t[h], part);
        }
    }
    if (p < NP) {
        for (int o = 16; o; o >>= 1) part += __shfl_xor_sync(0xffffffffu, part, o);
        if (lane == 0) {
            float z = part + b2t[0];
            float s = 1.f / (1.f + expf(-z));
            g_shlog[p * NB + w] = log1pf(-s + EPSV);
            g_relog[p * NB + w] = logf(s + EPSV);
        }
    }
}

// ------------------------- mma.sync GEMM + sum(exp) ----------------------------
__global__ void __launch_bounds__(256, 2) gemm_lse_mma(const float* __restrict__ b2w) {
    extern __shared__ __align__(128) char smem[];
    int tid = threadIdx.x;
    int wid = tid >> 5, lane = tid & 31;
    int wm = wid >> 2, wn = wid & 3;
    int grp = lane >> 2, qt = lane & 3;
    int rowBase = blockIdx.x * 128;
    int v0 = blockIdx.y * 128;

    unsigned int aBase[3], bBase[3];
    for (int s = 0; s < 3; s++) {
        aBase[s] = smem_u32(smem + s * STAGE_BYTES);
        bBase[s] = aBase[s] + A_BYTES;
    }
    int ar0 = tid >> 2, ac0 = (tid & 3) * 8;
    int bk0 = tid >> 4, bc0 = tid & 15;

    float acc[4][4][4];
    for (int mt = 0; mt < 4; mt++)
        for (int nt = 0; nt < 4; nt++)
            for (int e = 0; e < 4; e++) acc[mt][nt][e] = 0.f;

    int am = (lane & 7) + ((lane >> 3) & 1) * 8;
    int ak = (lane >> 4) * 8;
    int bRow = lane & 15;
    int bMat = lane >> 4;

    for (int pf = 0; pf < 2; pf++) {
        char* as = smem + pf * STAGE_BYTES;
        char* bs = as + A_BYTES;
        int k0 = pf * 32;
        __pipeline_memcpy_async(as + (ar0 * AS_LD + ac0) * 2,
                                &g_hwb[(rowBase + ar0) * HD + k0 + ac0], 16);
        __pipeline_memcpy_async(as + ((ar0 + 64) * AS_LD + ac0) * 2,
                                &g_hwb[(rowBase + ar0 + 64) * HD + k0 + ac0], 16);
        __pipeline_memcpy_async(bs + (bk0 * 128 + ((bc0 ^ (bk0 & 7)) * 8)) * 2,
                                &g_W2wb[(k0 + bk0) * NV + v0 + bc0 * 8], 16);
        __pipeline_memcpy_async(bs + ((bk0 + 16) * 128 + ((bc0 ^ ((bk0 + 16) & 7)) * 8)) * 2,
                                &g_W2wb[(k0 + bk0 + 16) * NV + v0 + bc0 * 8], 16);
        __pipeline_commit();
    }

    for (int kt = 0; kt < 16; kt++) {
        if (kt < 15) __pipeline_wait_prior(1);
        else __pipeline_wait_prior(0);
        __syncthreads();

        if (kt + 2 < 16) {
            int st = (kt + 2) % 3;
            char* as = smem + st * STAGE_BYTES;
            char* bs = as + A_BYTES;
            int k0 = (kt + 2) * 32;
            __pipeline_memcpy_async(as + (ar0 * AS_LD + ac0) * 2,
                                    &g_hwb[(rowBase + ar0) * HD + k0 + ac0], 16);
            __pipeline_memcpy_async(as + ((ar0 + 64) * AS_LD + ac0) * 2,
                                    &g_hwb[(rowBase + ar0 + 64) * HD + k0 + ac0], 16);
            __pipeline_memcpy_async(bs + (bk0 * 128 + ((bc0 ^ (bk0 & 7)) * 8)) * 2,
                                    &g_W2wb[(k0 + bk0) * NV + v0 + bc0 * 8], 16);
            __pipeline_memcpy_async(bs + ((bk0 + 16) * 128 + ((bc0 ^ ((bk0 + 16) & 7)) * 8)) * 2,
                                    &g_W2wb[(k0 + bk0 + 16) * NV + v0 + bc0 * 8], 16);
            __pipeline_commit();
        }

        int st = kt % 3;
        for (int kk = 0; kk < 32; kk += 16) {
            unsigned int afr[4][4];
            for (int mt = 0; mt < 4; mt++) {
                unsigned int aaddr = aBase[st] +
                    (unsigned int)(((wm * 64 + mt * 16 + am) * AS_LD + kk + ak) * 2);
                ldsm_x4(afr[mt][0], afr[mt][1], afr[mt][2], afr[mt][3], aaddr);
            }
            unsigned int bfr[4][2];
            int br = kk + bRow;
            for (int nb2 = 0; nb2 < 2; nb2++) {
                int ntx = nb2 * 2 + bMat;
                int chunk = (wn * 4 + ntx) ^ (br & 7);
                unsigned int baddr = bBase[st] +
                    (unsigned int)((br * 128 + chunk * 8) * 2);
                ldsm_x4t(bfr[nb2 * 2][0], bfr[nb2 * 2][1],
                         bfr[nb2 * 2 + 1][0], bfr[nb2 * 2 + 1][1], baddr);
            }
            for (int mt = 0; mt < 4; mt++)
                for (int nt = 0; nt < 4; nt++)
                    mma_bf16(acc[mt][nt][0], acc[mt][nt][1],
                             acc[mt][nt][2], acc[mt][nt][3],
                             afr[mt][0], afr[mt][1], afr[mt][2], afr[mt][3],
                             bfr[nt][0], bfr[nt][1]);
        }
    }

    // epilogue: exp + quad reduce + atomicAdd (acc rows: grp and grp+8)
    float bw[4][2];
    for (int nt = 0; nt < 4; nt++) {
        bw[nt][0] = b2w[v0 + wn * 32 + nt * 8 + 2 * qt];
        bw[nt][1] = b2w[v0 + wn * 32 + nt * 8 + 2 * qt + 1];
    }
    for (int mt = 0; mt < 4; mt++) {
        float s0 = 0.f, s1 = 0.f;
        for (int nt = 0; nt < 4; nt++) {
            s0 += __expf(acc[mt][nt][0] + bw[nt][0]) + __expf(acc[mt][nt][1] + bw[nt][1]);
            s1 += __expf(acc[mt][nt][2] + bw[nt][0]) + __expf(acc[mt][nt][3] + bw[nt][1]);
        }
        s0 += __shfl_xor_sync(0xffffffffu, s0, 1);
        s0 += __shfl_xor_sync(0xffffffffu, s0, 2);
        s1 += __shfl_xor_sync(0xffffffffu, s1, 1);
        s1 += __shfl_xor_sync(0xffffffffu, s1, 2);
        if (qt == 0) {
            int row = rowBase + wm * 64 + mt * 16 + grp;
            atomicAdd(&g_sum[row], s0);
            atomicAdd(&g_sum[row + 8], s1);
        }
    }
}

// ------------------------- gathered word logit + DP base cells (fused) ---------
__global__ void gather_base(const int* __restrict__ sentence,
                            const float* __restrict__ b2w) {
    int row = blockIdx.x * 8 + (threadIdx.x >> 5);
    int lane = threadIdx.x & 31;
    if (row >= NROW) return;
    int p = row >> 3, b = row & 7;
    int jw, i = 0, j = 0;
    if (p < NP) { i = inv_pair(p, j); jw = (j + 1 < LL) ? j + 1 : 0; }
    else jw = 1;
    int word = sentence[jw * NB + b];
    const __nv_bfloat16* hwrow = &g_hwb[(size_t)row * HD];
    float part = 0.f;
    for (int tt = 0; tt < 16; tt++) {
        int h = lane + tt * 32;
        part = fmaf(__bfloat162float(hwrow[h]),
                    __bfloat162float(g_W2wb[(size_t)h * NV + word]), part);
    }
    for (int o = 16; o; o >>= 1) part += __shfl_xor_sync(0xffffffffu, part, o);
    if (lane == 0) {
        float gw = part + b2w[word];
        float lse = logf(g_sum[row]);
        if (p < NP) {
            if (j <= LL - 2)
                g_table[((i * LL + j) * LL + (j + 1)) * NB + b] =
                    g_shlog[row] + gw - lse;
        } else {
            g_table[(0 * LL + 1) * NB + b] = gw - lse;
        }
    }
}

// ------------------------- full inside recursion, one persistent launch --------
__global__ void dp_all(float* __restrict__ out) {
    int blk = blockIdx.x;
    int tid = threadIdx.x;
    __shared__ float right[62 * 8];
    for (int gap = 2; gap <= LL - 1; gap++) {
        int nblk = LL - gap;
        if (blk < nblk) {
            int iv = blk;
            int jv = iv + gap;
            int nk = gap - 1;
            for (int m = tid; m < nk * 8; m += 512) {
                int d = m >> 3, b = m & 7;
                int k = iv + 1 + d;
                right[m] = g_table[((iv * LL + k) * LL + jv) * NB + b] +
                           g_relog[pidx(k, jv) * NB + b];
            }
            __syncthreads();
            int b = tid & 7, l = tid >> 3;
            const float* base = &g_table[(l * LL + iv) * LL * NB + b];
            // pass 1: max with 4 independent accumulators
            float m0 = -3.0e38f, m1 = -3.0e38f, m2 = -3.0e38f, m3 = -3.0e38f;
            int d = 0;
            for (; d + 4 <= nk; d += 4) {
                m0 = fmaxf(m0, base[(iv + 1 + d) * NB] + right[d * 8 + b]);
                m1 = fmaxf(m1, base[(iv + 2 + d) * NB] + right[(d + 1) * 8 + b]);
                m2 = fmaxf(m2, base[(iv + 3 + d) * NB] + right[(d + 2) * 8 + b]);
                m3 = fmaxf(m3, base[(iv + 4 + d) * NB] + right[(d + 3) * 8 + b]);
            }
            for (; d < nk; d++)
                m0 = fmaxf(m0, base[(iv + 1 + d) * NB] + right[d * 8 + b]);
            float mx = fmaxf(fmaxf(m0, m1), fmaxf(m2, m3));
            // pass 2: exp-sum with 4 independent accumulators
            float s0 = 0.f, s1 = 0.f, s2 = 0.f, s3 = 0.f;
            d = 0;
            for (; d + 4 <= nk; d += 4) {
                s0 += __expf(base[(iv + 1 + d) * NB] + right[d * 8 + b] - mx);
                s1 += __expf(base[(iv + 2 + d) * NB] + right[(d + 1) * 8 + b] - mx);
                s2 += __expf(base[(iv + 3 + d) * NB] + right[(d + 2) * 8 + b] - mx);
                s3 += __expf(base[(iv + 4 + d) * NB] + right[(d + 3) * 8 + b] - mx);
            }
            for (; d < nk; d++)
                s0 += __expf(base[(iv + 1 + d) * NB] + right[d * 8 + b] - mx);
            g_table[((l * LL + iv) * LL + jv) * NB + b] =
                mx + logf((s0 + s1) + (s2 + s3));
            __syncthreads();
        }
        if (tid == 0) {
            __threadfence();
            atomicAdd(&g_bar[gap], 1);
            while (*((volatile int*)&g_bar[gap]) < (int)gridDim.x) {}
            __threadfence();
        }
        __syncthreads();
    }
    if (blk == 0 && tid < NB)
        out[tid] = g_table[(0 * LL + (LL - 1)) * NB + tid];
}

// ------------------------- launch -------------------------
extern "C" void kernel_launch(void* const* d_in, const int* in_sizes, int n_in,
                              void* d_out, int out_size) {
    const float* enc = (const float*)d_in[0];
    const int* sentence = (const int*)d_in[1];
    const float* W1t = (const float*)d_in[2];
    const float* b1t = (const float*)d_in[3];
    const float* W2t = (const float*)d_in[4];
    const float* b2t = (const float*)d_in[5];
    const float* W1w = (const float*)d_in[6];
    const float* b1w = (const float*)d_in[7];
    const float* W2w = (const float*)d_in[8];
    const float* b2w = (const float*)d_in[9];
    float* out = (float*)d_out;

    cudaFuncSetAttribute(gemm_lse_mma, cudaFuncAttributeMaxDynamicSharedMemorySize,
                         SMEM_GEMM);
    cudaFuncSetAttribute(proj_mma, cudaFuncAttributeMaxDynamicSharedMemorySize,
                         SMEM_GEMM);

    init_all<<<4096, 256>>>(W2w, enc, W1t, W1w);               // launch 1
    proj_mma<<<dim3(4, 4, 4), 256, SMEM_GEMM>>>(0);            // launch 2
    pair_kernel<<<NP + 1, 256>>>(b1t, W2t, b2t, b1w);          // launch 3
    gemm_lse_mma<<<dim3(127, 64), 256, SMEM_GEMM>>>(b2w);      // launch 4 (ncu)
    gather_base<<<(NROW + 7) / 8, 256>>>(sentence, b2w);
    dp_all<<<62, 512>>>(out);
}

// round 14
// speedup vs baseline: 1.5962x; 1.0222x over previous
#include <cuda_runtime.h>
#include <cuda_bf16.h>
#include <cuda_pipeline.h>
#include <math.h>

#define LL 64
#define NB 8
#define HD 512
#define NV 8192
#define NP 2016                       // L*(L-1)/2 pairs
#define NROW ((NP + 1) * NB)          // 16136 rows (pairs + the (0,0) cell)
#define NROW_PAD (127 * 128)          // 16256, padded to GEMM row tiles
#define NEGV (-1e9f)
#define EPSV 4.5399929762484854e-05f  // exp(-10)

// ------------------------- device scratch -------------------------
__device__ __nv_bfloat16 g_Atb[LL * NB * HD];    // enc @ W1t[:H]  (bf16)
__device__ __nv_bfloat16 g_Btb[LL * NB * HD];    // enc @ W1t[H:]
__device__ __nv_bfloat16 g_Awb[LL * NB * HD];    // enc @ W1w[:H]
__device__ __nv_bfloat16 g_Bwb[LL * NB * HD];    // enc @ W1w[H:]
__device__ __nv_bfloat16 g_encb[LL * NB * HD];   // enc in bf16
__device__ __nv_bfloat16 g_W1tb[2 * HD * HD];    // W1t in bf16
__device__ __nv_bfloat16 g_W1wb[2 * HD * HD];    // W1w in bf16
__device__ __nv_bfloat16 g_hwb[NROW_PAD * HD];   // relu hidden (bf16)
__device__ __nv_bfloat16 g_W2wb[HD * NV];        // W2w in bf16, k-major [k][v]
__device__ __nv_bfloat16 g_wcolT[LL * NB * HD];  // W2w columns for sentence words
__device__ float g_shlog[NP * NB];
__device__ float g_relog[NP * NB];
__device__ float g_sum[NROW_PAD];
__device__ float g_table[LL * LL * LL * NB];
__device__ volatile int g_prog[LL];              // per-block completed gap

__device__ __forceinline__ int pidx(int i, int j) {
    return i * (2 * LL - 1 - i) / 2 + (j - i - 1);
}

__device__ __forceinline__ int inv_pair(int p, int& j) {
    int i = 0;
    while (p >= (LL - 1 - i)) { p -= (LL - 1 - i); i++; }
    j = i + 1 + p;
    return i;
}

// ------------------------- sanitized PTX helpers (no Jinja-active tokens) ------
__device__ __forceinline__ unsigned int smem_u32(const void* p) {
    unsigned int a;
    asm("{ .reg .u64 t; cvta.to.shared.u64 t, %1; cvt.u32.u64 %0, t; }"
        : "=r"(a) : "l"(p));
    return a;
}

__device__ __forceinline__ void ldsm_x4(unsigned int& r0, unsigned int& r1,
                                        unsigned int& r2, unsigned int& r3,
                                        unsigned int addr) {
    asm volatile(
        "ldmatrix.sync.aligned.m8n8.x4.shared.b16 { %0, %1, %2, %3 }, [ %4 ];"
        : "=r"(r0), "=r"(r1), "=r"(r2), "=r"(r3) : "r"(addr));
}

__device__ __forceinline__ void ldsm_x4t(unsigned int& r0, unsigned int& r1,
                                         unsigned int& r2, unsigned int& r3,
                                         unsigned int addr) {
    asm volatile(
        "ldmatrix.sync.aligned.m8n8.x4.trans.shared.b16 { %0, %1, %2, %3 }, [ %4 ];"
        : "=r"(r0), "=r"(r1), "=r"(r2), "=r"(r3) : "r"(addr));
}

__device__ __forceinline__ void mma_bf16(float& c0, float& c1, float& c2, float& c3,
                                         unsigned int a0, unsigned int a1,
                                         unsigned int a2, unsigned int a3,
                                         unsigned int b0, unsigned int b1) {
    asm volatile(
        "mma.sync.aligned.m16n8k16.row.col.f32.bf16.bf16.f32 "
        "{ %0, %1, %2, %3 }, { %4, %5, %6, %7 }, { %8, %9 }, { %0, %1, %2, %3 };"
        : "+f"(c0), "+f"(c1), "+f"(c2), "+f"(c3)
        : "r"(a0), "r"(a1), "r"(a2), "r"(a3), "r"(b0), "r"(b1));
}

// ------------------------- init + conversions (one launch) ---------------------
__global__ void init_all(const float* __restrict__ W, const float* __restrict__ enc,
                         const float* __restrict__ W1t, const float* __restrict__ W1w) {
    int idx = blockIdx.x * 256 + threadIdx.x;
    if (idx < (LL * LL * LL * NB) / 4) {
        float4 v4 = make_float4(NEGV, NEGV, NEGV, NEGV);
        *(float4*)(&g_table[idx * 4]) = v4;
    }
    if (idx < NROW_PAD / 4)
        *(float4*)(&g_sum[idx * 4]) = make_float4(0.f, 0.f, 0.f, 0.f);
    if (idx < ((NROW_PAD - NROW) * HD) / 4) {
        __nv_bfloat16 z = __float2bfloat16(0.f);
        __nv_bfloat16 o[4] = {z, z, z, z};
        *(unsigned long long*)(&g_hwb[NROW * HD + idx * 4]) = *(unsigned long long*)o;
    }
    if (idx < LL) g_prog[idx] = 1;   // base cells count as gap 1
    if (idx < (HD * NV) / 4) {
        int i = idx * 4;
        float4 v = *(const float4*)(W + i);
        __nv_bfloat16 o[4];
        o[0] = __float2bfloat16(v.x);
        o[1] = __float2bfloat16(v.y);
        o[2] = __float2bfloat16(v.z);
        o[3] = __float2bfloat16(v.w);
        *(unsigned long long*)(&g_W2wb[i]) = *(unsigned long long*)o;
    }
    if (idx < (LL * NB * HD) / 4) {
        int i = idx * 4;
        float4 v = *(const float4*)(enc + i);
        __nv_bfloat16 o[4];
        o[0] = __float2bfloat16(v.x);
        o[1] = __float2bfloat16(v.y);
        o[2] = __float2bfloat16(v.z);
        o[3] = __float2bfloat16(v.w);
        *(unsigned long long*)(&g_encb[i]) = *(unsigned long long*)o;
    }
    if (idx < (2 * HD * HD) / 4) {
        int i = idx * 4;
        float4 v = *(const float4*)(W1t + i);
        __nv_bfloat16 o[4];
        o[0] = __float2bfloat16(v.x);
        o[1] = __float2bfloat16(v.y);
        o[2] = __float2bfloat16(v.z);
        o[3] = __float2bfloat16(v.w);
        *(unsigned long long*)(&g_W1tb[i]) = *(unsigned long long*)o;
        float4 w = *(const float4*)(W1w + i);
        o[0] = __float2bfloat16(w.x);
        o[1] = __float2bfloat16(w.y);
        o[2] = __float2bfloat16(w.z);
        o[3] = __float2bfloat16(w.w);
        *(unsigned long long*)(&g_W1wb[i]) = *(unsigned long long*)o;
    }
}

// ------------------------- shared GEMM tile constants --------------------------
#define AS_LD 40
#define A_BYTES (128 * AS_LD * 2)          // 10240
#define B_BYTES (32 * 128 * 2)             // 8192
#define STAGE_BYTES (A_BYTES + B_BYTES)    // 18432
#define SMEM_GEMM (3 * STAGE_BYTES)        // 55296

// ------------------------- enc projections via mma (all 4, one launch) ---------
// C[512,512] = encb[512,512] @ W1b[koff:+512, :] (bf16 -> bf16 out).
__global__ void __launch_bounds__(256, 2) proj_mma(int dummy) {
    extern __shared__ __align__(128) char smem[];
    int which = blockIdx.z;
    const __nv_bfloat16* W = (which < 2) ? g_W1tb : g_W1wb;
    int koff = (which & 1) * HD;
    __nv_bfloat16* C = (which == 0) ? g_Atb : (which == 1) ? g_Btb
                        : (which == 2) ? g_Awb : g_Bwb;

    int tid = threadIdx.x;
    int wid = tid >> 5, lane = tid & 31;
    int wm = wid >> 2, wn = wid & 3;
    int grp = lane >> 2, qt = lane & 3;
    int rowBase = blockIdx.y * 128;
    int cb = blockIdx.x * 128;

    unsigned int aBase[3], bBase[3];
    for (int s = 0; s < 3; s++) {
        aBase[s] = smem_u32(smem + s * STAGE_BYTES);
        bBase[s] = aBase[s] + A_BYTES;
    }
    int ar0 = tid >> 2, ac0 = (tid & 3) * 8;
    int bk0 = tid >> 4, bc0 = tid & 15;

    float acc[4][4][4];
    for (int mt = 0; mt < 4; mt++)
        for (int nt = 0; nt < 4; nt++)
            for (int e = 0; e < 4; e++) acc[mt][nt][e] = 0.f;

    int am = (lane & 7) + ((lane >> 3) & 1) * 8;
    int ak = (lane >> 4) * 8;
    int bRow = lane & 15;
    int bMat = lane >> 4;

    for (int pf = 0; pf < 2; pf++) {
        char* as = smem + pf * STAGE_BYTES;
        char* bs = as + A_BYTES;
        int k0 = pf * 32;
        __pipeline_memcpy_async(as + (ar0 * AS_LD + ac0) * 2,
                                &g_encb[(rowBase + ar0) * HD + k0 + ac0], 16);
        __pipeline_memcpy_async(as + ((ar0 + 64) * AS_LD + ac0) * 2,
                                &g_encb[(rowBase + ar0 + 64) * HD + k0 + ac0], 16);
        __pipeline_memcpy_async(bs + (bk0 * 128 + ((bc0 ^ (bk0 & 7)) * 8)) * 2,
                                &W[(koff + k0 + bk0) * HD + cb + bc0 * 8], 16);
        __pipeline_memcpy_async(bs + ((bk0 + 16) * 128 + ((bc0 ^ ((bk0 + 16) & 7)) * 8)) * 2,
                                &W[(koff + k0 + bk0 + 16) * HD + cb + bc0 * 8], 16);
        __pipeline_commit();
    }

    for (int kt = 0; kt < 16; kt++) {
        if (kt < 15) __pipeline_wait_prior(1);
        else __pipeline_wait_prior(0);
        __syncthreads();
        if (kt + 2 < 16) {
            int st = (kt + 2) % 3;
            char* as = smem + st * STAGE_BYTES;
            char* bs = as + A_BYTES;
            int k0 = (kt + 2) * 32;
            __pipeline_memcpy_async(as + (ar0 * AS_LD + ac0) * 2,
                                    &g_encb[(rowBase + ar0) * HD + k0 + ac0], 16);
            __pipeline_memcpy_async(as + ((ar0 + 64) * AS_LD + ac0) * 2,
                                    &g_encb[(rowBase + ar0 + 64) * HD + k0 + ac0], 16);
            __pipeline_memcpy_async(bs + (bk0 * 128 + ((bc0 ^ (bk0 & 7)) * 8)) * 2,
                                    &W[(koff + k0 + bk0) * HD + cb + bc0 * 8], 16);
            __pipeline_memcpy_async(bs + ((bk0 + 16) * 128 + ((bc0 ^ ((bk0 + 16) & 7)) * 8)) * 2,
                                    &W[(koff + k0 + bk0 + 16) * HD + cb + bc0 * 8], 16);
            __pipeline_commit();
        }
        int st = kt % 3;
        for (int kk = 0; kk < 32; kk += 16) {
            unsigned int afr[4][4];
            for (int mt = 0; mt < 4; mt++) {
                unsigned int aaddr = aBase[st] +
                    (unsigned int)(((wm * 64 + mt * 16 + am) * AS_LD + kk + ak) * 2);
                ldsm_x4(afr[mt][0], afr[mt][1], afr[mt][2], afr[mt][3], aaddr);
            }
            unsigned int bfr[4][2];
            int br = kk + bRow;
            for (int nb2 = 0; nb2 < 2; nb2++) {
                int ntx = nb2 * 2 + bMat;
                int chunk = (wn * 4 + ntx) ^ (br & 7);
                unsigned int baddr = bBase[st] +
                    (unsigned int)((br * 128 + chunk * 8) * 2);
                ldsm_x4t(bfr[nb2 * 2][0], bfr[nb2 * 2][1],
                         bfr[nb2 * 2 + 1][0], bfr[nb2 * 2 + 1][1], baddr);
            }
            for (int mt = 0; mt < 4; mt++)
                for (int nt = 0; nt < 4; nt++)
                    mma_bf16(acc[mt][nt][0], acc[mt][nt][1],
                             acc[mt][nt][2], acc[mt][nt][3],
                             afr[mt][0], afr[mt][1], afr[mt][2], afr[mt][3],
                             bfr[nt][0], bfr[nt][1]);
        }
    }

    // epilogue: bf16 store (rows grp, grp+8 per fragment)
    for (int mt = 0; mt < 4; mt++)
        for (int nt = 0; nt < 4; nt++) {
            int m0 = rowBase + wm * 64 + mt * 16 + grp;
            int c0 = cb + wn * 32 + nt * 8 + 2 * qt;
            __nv_bfloat162 h0 = __floats2bfloat162_rn(acc[mt][nt][0], acc[mt][nt][1]);
            __nv_bfloat162 h1 = __floats2bfloat162_rn(acc[mt][nt][2], acc[mt][nt][3]);
            *(__nv_bfloat162*)(&C[m0 * HD + c0]) = h0;
            *(__nv_bfloat162*)(&C[(m0 + 8) * HD + c0]) = h1;
        }
}

// ------------------------- per-pair MLP heads (+ word-column transpose) --------
__global__ void pair_kernel(const float* __restrict__ b1t, const float* __restrict__ W2t,
                            const float* __restrict__ b2t, const float* __restrict__ b1w,
                            const int* __restrict__ sentence) {
    int p = blockIdx.x;
    if (p > NP) {
        // word-column transpose: block NP+1+jw copies W2w[:, sentence[jw,b]]
        int jw = p - (NP + 1);
        for (int l = 0; l < 16; l++) {
            int idx = threadIdx.x + l * 256;   // 4096 = NB * HD
            int b = idx >> 9, h = idx & (HD - 1);
            int word = sentence[jw * NB + b];
            g_wcolT[(jw * NB + b) * HD + h] = g_W2wb[(size_t)h * NV + word];
        }
        return;
    }
    int i = 0, j = 0;
    if (p < NP) i = inv_pair(p, j);
    int w = threadIdx.x >> 5;
    int lane = threadIdx.x & 31;
    const __nv_bfloat16* Ar = &g_Awb[(i * NB + w) * HD];
    const __nv_bfloat16* Br = &g_Bwb[(j * NB + w) * HD];
    const __nv_bfloat16* At = &g_Atb[(i * NB + w) * HD];
    const __nv_bfloat16* Bt = &g_Btb[(j * NB + w) * HD];
    __nv_bfloat16* hwrow = &g_hwb[(p * NB + w) * HD];
    float part = 0.f;
    for (int t = 0; t < 16; t++) {
        int h = lane + t * 32;
        float hw = fmaxf(__bfloat162float(Ar[h]) + __bfloat162float(Br[h]) + b1w[h], 0.f);
        hwrow[h] = __float2bfloat16(hw);
        if (p < NP) {
            float ht = fmaxf(__bfloat162float(At[h]) + __bfloat162float(Bt[h]) + b1t[h], 0.f);
            part = fmaf(ht, W2t[h], part);
        }
    }
    if (p < NP) {
        for (int o = 16; o; o >>= 1) part += __shfl_xor_sync(0xffffffffu, part, o);
        if (lane == 0) {
            float z = part + b2t[0];
            float s = 1.f / (1.f + expf(-z));
            g_shlog[p * NB + w] = log1pf(-s + EPSV);
            g_relog[p * NB + w] = logf(s + EPSV);
        }
    }
}

// ------------------------- mma.sync GEMM + sum(exp) ----------------------------
__global__ void __launch_bounds__(256, 2) gemm_lse_mma(const float* __restrict__ b2w) {
    extern __shared__ __align__(128) char smem[];
    int tid = threadIdx.x;
    int wid = tid >> 5, lane = tid & 31;
    int wm = wid >> 2, wn = wid & 3;
    int grp = lane >> 2, qt = lane & 3;
    int rowBase = blockIdx.x * 128;
    int v0 = blockIdx.y * 128;

    unsigned int aBase[3], bBase[3];
    for (int s = 0; s < 3; s++) {
        aBase[s] = smem_u32(smem + s * STAGE_BYTES);
        bBase[s] = aBase[s] + A_BYTES;
    }
    int ar0 = tid >> 2, ac0 = (tid & 3) * 8;
    int bk0 = tid >> 4, bc0 = tid & 15;

    float acc[4][4][4];
    for (int mt = 0; mt < 4; mt++)
        for (int nt = 0; nt < 4; nt++)
            for (int e = 0; e < 4; e++) acc[mt][nt][e] = 0.f;

    int am = (lane & 7) + ((lane >> 3) & 1) * 8;
    int ak = (lane >> 4) * 8;
    int bRow = lane & 15;
    int bMat = lane >> 4;

    for (int pf = 0; pf < 2; pf++) {
        char* as = smem + pf * STAGE_BYTES;
        char* bs = as + A_BYTES;
        int k0 = pf * 32;
        __pipeline_memcpy_async(as + (ar0 * AS_LD + ac0) * 2,
                                &g_hwb[(rowBase + ar0) * HD + k0 + ac0], 16);
        __pipeline_memcpy_async(as + ((ar0 + 64) * AS_LD + ac0) * 2,
                                &g_hwb[(rowBase + ar0 + 64) * HD + k0 + ac0], 16);
        __pipeline_memcpy_async(bs + (bk0 * 128 + ((bc0 ^ (bk0 & 7)) * 8)) * 2,
                                &g_W2wb[(k0 + bk0) * NV + v0 + bc0 * 8], 16);
        __pipeline_memcpy_async(bs + ((bk0 + 16) * 128 + ((bc0 ^ ((bk0 + 16) & 7)) * 8)) * 2,
                                &g_W2wb[(k0 + bk0 + 16) * NV + v0 + bc0 * 8], 16);
        __pipeline_commit();
    }

    for (int kt = 0; kt < 16; kt++) {
        if (kt < 15) __pipeline_wait_prior(1);
        else __pipeline_wait_prior(0);
        __syncthreads();

        if (kt + 2 < 16) {
            int st = (kt + 2) % 3;
            char* as = smem + st * STAGE_BYTES;
            char* bs = as + A_BYTES;
            int k0 = (kt + 2) * 32;
            __pipeline_memcpy_async(as + (ar0 * AS_LD + ac0) * 2,
                                    &g_hwb[(rowBase + ar0) * HD + k0 + ac0], 16);
            __pipeline_memcpy_async(as + ((ar0 + 64) * AS_LD + ac0) * 2,
                                    &g_hwb[(rowBase + ar0 + 64) * HD + k0 + ac0], 16);
            __pipeline_memcpy_async(bs + (bk0 * 128 + ((bc0 ^ (bk0 & 7)) * 8)) * 2,
                                    &g_W2wb[(k0 + bk0) * NV + v0 + bc0 * 8], 16);
            __pipeline_memcpy_async(bs + ((bk0 + 16) * 128 + ((bc0 ^ ((bk0 + 16) & 7)) * 8)) * 2,
                                    &g_W2wb[(k0 + bk0 + 16) * NV + v0 + bc0 * 8], 16);
            __pipeline_commit();
        }

        int st = kt % 3;
        for (int kk = 0; kk < 32; kk += 16) {
            unsigned int afr[4][4];
            for (int mt = 0; mt < 4; mt++) {
                unsigned int aaddr = aBase[st] +
                    (unsigned int)(((wm * 64 + mt * 16 + am) * AS_LD + kk + ak) * 2);
                ldsm_x4(afr[mt][0], afr[mt][1], afr[mt][2], afr[mt][3], aaddr);
            }
            unsigned int bfr[4][2];
            int br = kk + bRow;
            for (int nb2 = 0; nb2 < 2; nb2++) {
                int ntx = nb2 * 2 + bMat;
                int chunk = (wn * 4 + ntx) ^ (br & 7);
                unsigned int baddr = bBase[st] +
                    (unsigned int)((br * 128 + chunk * 8) * 2);
                ldsm_x4t(bfr[nb2 * 2][0], bfr[nb2 * 2][1],
                         bfr[nb2 * 2 + 1][0], bfr[nb2 * 2 + 1][1], baddr);
            }
            for (int mt = 0; mt < 4; mt++)
                for (int nt = 0; nt < 4; nt++)
                    mma_bf16(acc[mt][nt][0], acc[mt][nt][1],
                             acc[mt][nt][2], acc[mt][nt][3],
                             afr[mt][0], afr[mt][1], afr[mt][2], afr[mt][3],
                             bfr[nt][0], bfr[nt][1]);
        }
    }

    // epilogue: exp + quad reduce + atomicAdd (acc rows: grp and grp+8)
    float bw[4][2];
    for (int nt = 0; nt < 4; nt++) {
        bw[nt][0] = b2w[v0 + wn * 32 + nt * 8 + 2 * qt];
        bw[nt][1] = b2w[v0 + wn * 32 + nt * 8 + 2 * qt + 1];
    }
    for (int mt = 0; mt < 4; mt++) {
        float s0 = 0.f, s1 = 0.f;
        for (int nt = 0; nt < 4; nt++) {
            s0 += __expf(acc[mt][nt][0] + bw[nt][0]) + __expf(acc[mt][nt][1] + bw[nt][1]);
            s1 += __expf(acc[mt][nt][2] + bw[nt][0]) + __expf(acc[mt][nt][3] + bw[nt][1]);
        }
        s0 += __shfl_xor_sync(0xffffffffu, s0, 1);
        s0 += __shfl_xor_sync(0xffffffffu, s0, 2);
        s1 += __shfl_xor_sync(0xffffffffu, s1, 1);
        s1 += __shfl_xor_sync(0xffffffffu, s1, 2);
        if (qt == 0) {
            int row = rowBase + wm * 64 + mt * 16 + grp;
            atomicAdd(&g_sum[row], s0);
            atomicAdd(&g_sum[row + 8], s1);
        }
    }
}

// ------------------------- gathered word logit + DP base cells (fused) ---------
__global__ void gather_base(const int* __restrict__ sentence,
                            const float* __restrict__ b2w) {
    int row = blockIdx.x * 8 + (threadIdx.x >> 5);
    int lane = threadIdx.x & 31;
    if (row >= NROW) return;
    int p = row >> 3, b = row & 7;
    int jw, i = 0, j = 0;
    if (p < NP) { i = inv_pair(p, j); jw = (j + 1 < LL) ? j + 1 : 0; }
    else jw = 1;
    int word = sentence[jw * NB + b];
    const __nv_bfloat16* hwrow = &g_hwb[(size_t)row * HD];
    const __nv_bfloat16* wc = &g_wcolT[(jw * NB + b) * HD];
    float part = 0.f;
    for (int tt = 0; tt < 16; tt++) {
        int h = lane + tt * 32;
        part = fmaf(__bfloat162float(hwrow[h]), __bfloat162float(wc[h]), part);
    }
    for (int o = 16; o; o >>= 1) part += __shfl_xor_sync(0xffffffffu, part, o);
    if (lane == 0) {
        float gw = part + b2w[word];
        float lse = logf(g_sum[row]);
        if (p < NP) {
            if (j <= LL - 2)
                g_table[((i * LL + j) * LL + (j + 1)) * NB + b] =
                    g_shlog[row] + gw - lse;
        } else {
            g_table[(0 * LL + 1) * NB + b] = gw - lse;
        }
    }
}

// ------------------------- inside recursion: wavefront, no global barrier ------
// Block iv handles column iv. At gap g it reads its OWN prior cells (left
// factors) and foreign cells (iv, k, jv) written by block k at gap jv-k.
// Readiness is tracked via g_prog[k] (monotone). Deps point strictly to
// higher block ids -> no deadlock; all 62 blocks co-resident.
__global__ void dp_all(float* __restrict__ out) {
    int iv = blockIdx.x;
    int tid = threadIdx.x;
    __shared__ float right[62 * 8];
    int maxgap = (LL - 1) - iv;
    for (int gap = 2; gap <= maxgap; gap++) {
        int jv = iv + gap;
        int nk = gap - 1;
        // wait for producers: d in [1, gap-2] needs prog[iv+d] >= gap-d
        if (tid >= 1 && tid <= gap - 2) {
            while (g_prog[iv + tid] < gap - tid) {}
        }
        __syncthreads();
        if (tid == 0) __threadfence();   // acquire + L1 invalidate (CCTL.IVALL)
        __syncthreads();

        for (int m = tid; m < nk * 8; m += 512) {
            int d = m >> 3, b = m & 7;
            int k = iv + 1 + d;
            right[m] = g_table[((iv * LL + k) * LL + jv) * NB + b] +
                       g_relog[pidx(k, jv) * NB + b];
        }
        __syncthreads();
        int b = tid & 7, l = tid >> 3;
        const float* base = &g_table[(l * LL + iv) * LL * NB + b];
        float m0 = -3.0e38f, m1 = -3.0e38f, m2 = -3.0e38f, m3 = -3.0e38f;
        int d = 0;
        for (; d + 4 <= nk; d += 4) {
            m0 = fmaxf(m0, base[(iv + 1 + d) * NB] + right[d * 8 + b]);
            m1 = fmaxf(m1, base[(iv + 2 + d) * NB] + right[(d + 1) * 8 + b]);
            m2 = fmaxf(m2, base[(iv + 3 + d) * NB] + right[(d + 2) * 8 + b]);
            m3 = fmaxf(m3, base[(iv + 4 + d) * NB] + right[(d + 3) * 8 + b]);
        }
        for (; d < nk; d++)
            m0 = fmaxf(m0, base[(iv + 1 + d) * NB] + right[d * 8 + b]);
        float mx = fmaxf(fmaxf(m0, m1), fmaxf(m2, m3));
        float s0 = 0.f, s1 = 0.f, s2 = 0.f, s3 = 0.f;
        d = 0;
        for (; d + 4 <= nk; d += 4) {
            s0 += __expf(base[(iv + 1 + d) * NB] + right[d * 8 + b] - mx);
            s1 += __expf(base[(iv + 2 + d) * NB] + right[(d + 1) * 8 + b] - mx);
            s2 += __expf(base[(iv + 3 + d) * NB] + right[(d + 2) * 8 + b] - mx);
            s3 += __expf(base[(iv + 4 + d) * NB] + right[(d + 3) * 8 + b] - mx);
        }
        for (; d < nk; d++)
            s0 += __expf(base[(iv + 1 + d) * NB] + right[d * 8 + b] - mx);
        g_table[((l * LL + iv) * LL + jv) * NB + b] =
            mx + logf((s0 + s1) + (s2 + s3));
        __syncthreads();   // all writes + right reads complete
        if (tid == 0) {
            __threadfence();      // publish table writes
            g_prog[iv] = gap;     // release
        }
    }
    if (iv == 0 && tid < NB)
        out[tid] = g_table[(0 * LL + (LL - 1)) * NB + tid];
}

// ------------------------- launch -------------------------
extern "C" void kernel_launch(void* const* d_in, const int* in_sizes, int n_in,
                              void* d_out, int out_size) {
    const float* enc = (const float*)d_in[0];
    const int* sentence = (const int*)d_in[1];
    const float* W1t = (const float*)d_in[2];
    const float* b1t = (const float*)d_in[3];
    const float* W2t = (const float*)d_in[4];
    const float* b2t = (const float*)d_in[5];
    const float* W1w = (const float*)d_in[6];
    const float* b1w = (const float*)d_in[7];
    const float* W2w = (const float*)d_in[8];
    const float* b2w = (const float*)d_in[9];
    float* out = (float*)d_out;

    cudaFuncSetAttribute(gemm_lse_mma, cudaFuncAttributeMaxDynamicSharedMemorySize,
                         SMEM_GEMM);
    cudaFuncSetAttribute(proj_mma, cudaFuncAttributeMaxDynamicSharedMemorySize,
                         SMEM_GEMM);

    init_all<<<4096, 256>>>(W2w, enc, W1t, W1w);                 // launch 1
    proj_mma<<<dim3(4, 4, 4), 256, SMEM_GEMM>>>(0);              // launch 2
    pair_kernel<<<NP + 1 + LL, 256>>>(b1t, W2t, b2t, b1w, sentence);  // launch 3
    gemm_lse_mma<<<dim3(127, 64), 256, SMEM_GEMM>>>(b2w);        // launch 4 (ncu)
    gather_base<<<(NROW + 7) / 8, 256>>>(sentence, b2w);
    dp_all<<<62, 512>>>(out);
}